// round 4
// baseline (speedup 1.0000x reference)
#include <cuda_runtime.h>

// Problem constants
#define TT 128
#define BB 512
#define DD 768

typedef unsigned long long ull;

// Scratch (device globals — no runtime allocation allowed)
__device__ float g_G[(size_t)TT * BB * 64];  // gates [t][b][64]: 0-31 fwd, 32-63 bwd (bias included)
__device__ float g_h[(size_t)TT * BB * 16];  // bi-LSTM hidden [t][b][16]
__device__ float g_z[(size_t)TT * BB * 16];  // ptr-LSTM hidden [t][b][16]

__device__ __forceinline__ float sigmoidf_fast(float x) {
    return 1.0f / (1.0f + __expf(-x));
}

// ---- packed f32x2 helpers (sm_103a full-rate fp32 path) ----
__device__ __forceinline__ ull fma2_(ull a, ull b, ull c) {
    ull d;
    asm("fma.rn.f32x2 %0, %1, %2, %3;" : "=l"(d) : "l"(a), "l"(b), "l"(c));
    return d;
}
__device__ __forceinline__ ull pack2(float x) {
    ull d;
    asm("mov.b64 %0, {%1, %1};" : "=l"(d) : "f"(x));
    return d;
}
__device__ __forceinline__ float2 unpk(ull v) {
    float lo, hi;
    asm("mov.b64 {%0, %1}, %2;" : "=f"(lo), "=f"(hi) : "l"(v));
    return make_float2(lo, hi);
}

// ---------------------------------------------------------------------------
// K1 v3: G = X @ Wcat^T + bias. X: 65536x768, Wcat 64x768.
// grid 512, 128 thr, BM=128 BN=64 BK=16, microtile 8x8, double-buffered smem
// (one barrier per iter), register prefetch. acc = 32 ull (64 regs) so 3
// blocks/SM stay resident.
// ---------------------------------------------------------------------------
__global__ __launch_bounds__(128) void k1_proj(
    const float* __restrict__ X,
    const float* __restrict__ Wf, const float* __restrict__ Wb,
    const float* __restrict__ bf1, const float* __restrict__ bf2,
    const float* __restrict__ bb1, const float* __restrict__ bb2)
{
    __shared__ float As[2][16][128];   // [stage][k][m] 16KB
    __shared__ float Bs[2][16][64];    // [stage][k][n] 8KB
    __shared__ float bias[64];

    const int tid = threadIdx.x;
    const int r0  = blockIdx.x * 128;

    if (tid < 64)
        bias[tid] = (tid < 32) ? (bf1[tid] + bf2[tid])
                               : (bb1[tid - 32] + bb2[tid - 32]);

    // loaders: thread tid loads X row (r0+tid), 16 floats per iter;
    //          wj = tid>>1 loads gate-row wj, 8 floats (half the 16-k chunk).
    const float* xrow = X + (size_t)(r0 + tid) * DD;
    const int wj = tid >> 1;
    const int wh = tid & 1;
    const float* wrow = ((wj < 32) ? (Wf + (size_t)wj * DD)
                                   : (Wb + (size_t)(wj - 32) * DD)) + wh * 8;

    // fill stage 0
    {
        float4 x0 = *(const float4*)(xrow + 0);
        float4 x1 = *(const float4*)(xrow + 4);
        float4 x2 = *(const float4*)(xrow + 8);
        float4 x3 = *(const float4*)(xrow + 12);
        float4 w0 = *(const float4*)(wrow + 0);
        float4 w1 = *(const float4*)(wrow + 4);
        As[0][0][tid] = x0.x;  As[0][1][tid] = x0.y;  As[0][2][tid] = x0.z;  As[0][3][tid] = x0.w;
        As[0][4][tid] = x1.x;  As[0][5][tid] = x1.y;  As[0][6][tid] = x1.z;  As[0][7][tid] = x1.w;
        As[0][8][tid] = x2.x;  As[0][9][tid] = x2.y;  As[0][10][tid] = x2.z; As[0][11][tid] = x2.w;
        As[0][12][tid] = x3.x; As[0][13][tid] = x3.y; As[0][14][tid] = x3.z; As[0][15][tid] = x3.w;
        Bs[0][wh * 8 + 0][wj] = w0.x; Bs[0][wh * 8 + 1][wj] = w0.y;
        Bs[0][wh * 8 + 2][wj] = w0.z; Bs[0][wh * 8 + 3][wj] = w0.w;
        Bs[0][wh * 8 + 4][wj] = w1.x; Bs[0][wh * 8 + 5][wj] = w1.y;
        Bs[0][wh * 8 + 6][wj] = w1.z; Bs[0][wh * 8 + 7][wj] = w1.w;
    }
    __syncthreads();

    const int ty = tid >> 3;   // 0..15 -> rows ty*8..+7
    const int tx = tid & 7;    // 0..7  -> cols tx*8..+7

    ull acc[8][4];
#pragma unroll
    for (int r = 0; r < 8; r++)
#pragma unroll
        for (int c = 0; c < 4; c++) acc[r][c] = 0ull;

    for (int s = 0; s < 48; s++) {
        const int p = s & 1;

        // prefetch next tile into registers (consumed after compute)
        float4 x0, x1, x2, x3, w0, w1;
        if (s + 1 < 48) {
            const int kn = (s + 1) * 16;
            x0 = *(const float4*)(xrow + kn + 0);
            x1 = *(const float4*)(xrow + kn + 4);
            x2 = *(const float4*)(xrow + kn + 8);
            x3 = *(const float4*)(xrow + kn + 12);
            w0 = *(const float4*)(wrow + kn + 0);
            w1 = *(const float4*)(wrow + kn + 4);
        }

#pragma unroll
        for (int k = 0; k < 16; k++) {
            float xv[8];
            *(float4*)&xv[0] = *(const float4*)&As[p][k][ty * 8];
            *(float4*)&xv[4] = *(const float4*)&As[p][k][ty * 8 + 4];
            ull w2[4];
            {
                const ulonglong2* wp = (const ulonglong2*)&Bs[p][k][tx * 8];
                ulonglong2 a = wp[0], b = wp[1];
                w2[0] = a.x; w2[1] = a.y; w2[2] = b.x; w2[3] = b.y;
            }
#pragma unroll
            for (int r = 0; r < 8; r++) {
                ull x2p = pack2(xv[r]);
#pragma unroll
                for (int c = 0; c < 4; c++)
                    acc[r][c] = fma2_(x2p, w2[c], acc[r][c]);
            }
        }

        if (s + 1 < 48) {
            const int q = p ^ 1;
            As[q][0][tid] = x0.x;  As[q][1][tid] = x0.y;  As[q][2][tid] = x0.z;  As[q][3][tid] = x0.w;
            As[q][4][tid] = x1.x;  As[q][5][tid] = x1.y;  As[q][6][tid] = x1.z;  As[q][7][tid] = x1.w;
            As[q][8][tid] = x2.x;  As[q][9][tid] = x2.y;  As[q][10][tid] = x2.z; As[q][11][tid] = x2.w;
            As[q][12][tid] = x3.x; As[q][13][tid] = x3.y; As[q][14][tid] = x3.z; As[q][15][tid] = x3.w;
            Bs[q][wh * 8 + 0][wj] = w0.x; Bs[q][wh * 8 + 1][wj] = w0.y;
            Bs[q][wh * 8 + 2][wj] = w0.z; Bs[q][wh * 8 + 3][wj] = w0.w;
            Bs[q][wh * 8 + 4][wj] = w1.x; Bs[q][wh * 8 + 5][wj] = w1.y;
            Bs[q][wh * 8 + 6][wj] = w1.z; Bs[q][wh * 8 + 7][wj] = w1.w;
        }
        __syncthreads();
    }

    // epilogue: bias + two float4 stores per row
    float bl[8];
#pragma unroll
    for (int i = 0; i < 8; i++) bl[i] = bias[tx * 8 + i];
#pragma unroll
    for (int r = 0; r < 8; r++) {
        float* gp = g_G + (size_t)(r0 + ty * 8 + r) * 64 + tx * 8;
        float2 p0 = unpk(acc[r][0]);
        float2 p1 = unpk(acc[r][1]);
        float2 p2 = unpk(acc[r][2]);
        float2 p3 = unpk(acc[r][3]);
        *(float4*)(gp + 0) = make_float4(p0.x + bl[0], p0.y + bl[1],
                                         p1.x + bl[2], p1.y + bl[3]);
        *(float4*)(gp + 4) = make_float4(p2.x + bl[4], p2.y + bl[5],
                                         p3.x + bl[6], p3.y + bl[7]);
    }
}

// ---------------------------------------------------------------------------
// K2: bi-LSTM scans (fwd + bwd), one warp per (batch item, direction).
// ---------------------------------------------------------------------------
__global__ __launch_bounds__(128) void k2_bilstm(
    const float* __restrict__ Whhf, const float* __restrict__ Whhb)
{
    const unsigned FULL = 0xffffffffu;
    int warp = blockIdx.x * (blockDim.x >> 5) + (threadIdx.x >> 5); // 0..1023
    int lane = threadIdx.x & 31;
    int dir  = warp >> 9;
    int b    = warp & 511;

    const float* Whh = dir ? Whhb : Whhf;
    float w[8];
#pragma unroll
    for (int k = 0; k < 8; k++) w[k] = Whh[lane * 8 + k];

    float hrep[8];
#pragma unroll
    for (int k = 0; k < 8; k++) hrep[k] = 0.0f;
    float c = 0.0f;

    const int coloff = dir * 32 + lane;
    int t0 = dir ? (TT - 1) : 0;
    float gcur = g_G[((size_t)t0 * BB + b) * 64 + coloff];

    for (int s = 0; s < TT; s++) {
        int t = dir ? (TT - 1 - s) : s;
        float gnext = 0.0f;
        if (s + 1 < TT) {
            int tn = dir ? (TT - 2 - s) : (s + 1);
            gnext = g_G[((size_t)tn * BB + b) * 64 + coloff];
        }
        float gate = gcur;
#pragma unroll
        for (int k = 0; k < 8; k++) gate = fmaf(hrep[k], w[k], gate);

        float a = (lane >= 16 && lane < 24) ? tanhf(gate) : sigmoidf_fast(gate);
        float fv = __shfl_sync(FULL, a, lane + 8);
        float gv = __shfl_sync(FULL, a, lane + 16);
        float ov = __shfl_sync(FULL, a, lane + 24);

        float hnew = 0.0f;
        if (lane < 8) {
            c = fmaf(fv, c, a * gv);
            hnew = ov * tanhf(c);
            g_h[((size_t)t * BB + b) * 16 + dir * 8 + lane] = hnew;
        }
#pragma unroll
        for (int k = 0; k < 8; k++) hrep[k] = __shfl_sync(FULL, hnew, k);
        gcur = gnext;
    }
}

// ---------------------------------------------------------------------------
// K4: ptr-LSTM scan, one warp per batch item.
// ---------------------------------------------------------------------------
__global__ __launch_bounds__(128) void k4_ptr(
    const float* __restrict__ Wih, const float* __restrict__ Whh,
    const float* __restrict__ b1, const float* __restrict__ b2)
{
    const unsigned FULL = 0xffffffffu;
    int warp = blockIdx.x * (blockDim.x >> 5) + (threadIdx.x >> 5); // 0..511
    int lane = threadIdx.x & 31;
    int b    = warp;

    const int r0 = lane, r1 = lane + 32;
    float wi0[16], wi1[16], wh0[16], wh1[16];
#pragma unroll
    for (int k = 0; k < 16; k++) {
        wi0[k] = Wih[r0 * 16 + k];
        wi1[k] = Wih[r1 * 16 + k];
        wh0[k] = Whh[r0 * 16 + k];
        wh1[k] = Whh[r1 * 16 + k];
    }
    const float bias0 = b1[r0] + b2[r0];
    const float bias1 = b1[r1] + b2[r1];

    float zrep[16];
#pragma unroll
    for (int k = 0; k < 16; k++) zrep[k] = 0.0f;
    float c = 0.0f;

    const float4* hp = (const float4*)g_h;
    size_t base = ((size_t)0 * BB + b) * 4;
    float4 x0 = hp[base + 0], x1 = hp[base + 1], x2 = hp[base + 2], x3 = hp[base + 3];

    for (int t = 0; t < TT; t++) {
        float4 n0 = x0, n1 = x1, n2 = x2, n3 = x3;
        if (t + 1 < TT) {
            size_t nb = ((size_t)(t + 1) * BB + b) * 4;
            n0 = hp[nb + 0]; n1 = hp[nb + 1]; n2 = hp[nb + 2]; n3 = hp[nb + 3];
        }
        float xin[16] = {x0.x, x0.y, x0.z, x0.w, x1.x, x1.y, x1.z, x1.w,
                         x2.x, x2.y, x2.z, x2.w, x3.x, x3.y, x3.z, x3.w};
        float u0 = bias0, u1 = bias1;
#pragma unroll
        for (int k = 0; k < 16; k++) {
            u0 = fmaf(xin[k], wi0[k], u0);
            u1 = fmaf(xin[k], wi1[k], u1);
        }
#pragma unroll
        for (int k = 0; k < 16; k++) {
            u0 = fmaf(zrep[k], wh0[k], u0);
            u1 = fmaf(zrep[k], wh1[k], u1);
        }
        float a0 = sigmoidf_fast(u0);
        float a1 = (lane < 16) ? tanhf(u1) : sigmoidf_fast(u1);
        float fv = __shfl_sync(FULL, a0, lane + 16);
        float ov = __shfl_sync(FULL, a1, lane + 16);

        float zn = 0.0f;
        if (lane < 16) {
            c = fmaf(fv, c, a0 * a1);
            zn = ov * tanhf(c);
            g_z[((size_t)t * BB + b) * 16 + lane] = zn;
        }
#pragma unroll
        for (int k = 0; k < 16; k++) zrep[k] = __shfl_sync(FULL, zn, k);
        x0 = n0; x1 = n1; x2 = n2; x3 = n3;
    }
}

// ---------------------------------------------------------------------------
// K5 v3: per-timestep attention + scoring. One block per t, 256 threads,
// each thread owns 2 query rows (bq, bq+256). Scores bounded (|S|<=16):
// no max pass. E stride 516 -> colsum banks = lane id (conflict-free).
// ---------------------------------------------------------------------------
#define K5_EPAD 516
#define K5_SMEM_FLOATS (8192 + 8192 + 64 * K5_EPAD + 256 + 64 + 528)
#define K5_SMEM_BYTES  (K5_SMEM_FLOATS * 4)

extern __shared__ float k5_smem[];

__global__ __launch_bounds__(256, 1) void k5_attn(
    const float* __restrict__ Wh, const float* __restrict__ We,
    const float* __restrict__ Wv, float* __restrict__ out)
{
    float* hs  = k5_smem;                  // 512*16
    float* zs  = hs + 8192;                // 512*16
    float* E   = zs + 8192;                // 64 * 516
    float* red = E + 64 * K5_EPAD;         // 256
    float* inv = red + 256;                // 64
    float* ws  = inv + 64;                 // Wh[256] | We[256] | Wv[16]

    const int tid = threadIdx.x;
    const int t   = blockIdx.x;

    const float4* hg = (const float4*)(g_h + (size_t)t * BB * 16);
    const float4* zg = (const float4*)(g_z + (size_t)t * BB * 16);
    float4* hs4 = (float4*)hs;
    float4* zs4 = (float4*)zs;
#pragma unroll
    for (int i = 0; i < 8; i++) {
        hs4[i * 256 + tid] = hg[i * 256 + tid];
        zs4[i * 256 + tid] = zg[i * 256 + tid];
    }
    ws[tid]       = Wh[tid];
    ws[256 + tid] = We[tid];
    if (tid < 16) ws[512 + tid] = Wv[tid];
    __syncthreads();

    const int bq0 = tid;
    const int bq1 = tid + 256;
    ull hra[8], hrb[8];
    {
        const ulonglong2* ha = (const ulonglong2*)(hs + bq0 * 16);
        const ulonglong2* hb = (const ulonglong2*)(hs + bq1 * 16);
#pragma unroll
        for (int i = 0; i < 4; i++) {
            ulonglong2 va = ha[i], vb = hb[i];
            hra[2 * i] = va.x; hra[2 * i + 1] = va.y;
            hrb[2 * i] = vb.x; hrb[2 * i + 1] = vb.y;
        }
    }
    ull ctxa[8], ctxb[8];
#pragma unroll
    for (int d = 0; d < 8; d++) { ctxa[d] = 0ull; ctxb[d] = 0ull; }

    for (int tile = 0; tile < 8; tile++) {
        // --- scores + exp for 64 softmax-columns, 2 query rows/thread ---
#pragma unroll 4
        for (int cc = 0; cc < 64; cc++) {
            const ulonglong2* zp = (const ulonglong2*)(zs + (tile * 64 + cc) * 16);
            ulonglong2 z0 = zp[0], z1 = zp[1], z2 = zp[2], z3 = zp[3];
            ull da0 = 0ull, da1 = 0ull, db0 = 0ull, db1 = 0ull;
            da0 = fma2_(hra[0], z0.x, da0); da1 = fma2_(hra[1], z0.y, da1);
            da0 = fma2_(hra[2], z1.x, da0); da1 = fma2_(hra[3], z1.y, da1);
            da0 = fma2_(hra[4], z2.x, da0); da1 = fma2_(hra[5], z2.y, da1);
            da0 = fma2_(hra[6], z3.x, da0); da1 = fma2_(hra[7], z3.y, da1);
            db0 = fma2_(hrb[0], z0.x, db0); db1 = fma2_(hrb[1], z0.y, db1);
            db0 = fma2_(hrb[2], z1.x, db0); db1 = fma2_(hrb[3], z1.y, db1);
            db0 = fma2_(hrb[4], z2.x, db0); db1 = fma2_(hrb[5], z2.y, db1);
            db0 = fma2_(hrb[6], z3.x, db0); db1 = fma2_(hrb[7], z3.y, db1);
            float2 a0 = unpk(da0), a1 = unpk(da1);
            float2 b0 = unpk(db0), b1 = unpk(db1);
            E[cc * K5_EPAD + bq0] = __expf((a0.x + a0.y) + (a1.x + a1.y));
            E[cc * K5_EPAD + bq1] = __expf((b0.x + b0.y) + (b1.x + b1.y));
        }
        __syncthreads();
        // --- column sums (over b): bank = lane, conflict-free ---
        {
            int cc = tid >> 2, seg = tid & 3;
            float s0 = 0.0f, s1 = 0.0f, s2 = 0.0f, s3 = 0.0f;
            const float* ep = E + cc * K5_EPAD + seg;
#pragma unroll 8
            for (int j = 0; j < 32; j++) {
                s0 += ep[16 * j + 0];
                s1 += ep[16 * j + 4];
                s2 += ep[16 * j + 8];
                s3 += ep[16 * j + 12];
            }
            red[tid] = (s0 + s1) + (s2 + s3);
        }
        __syncthreads();
        if (tid < 64) {
            float s = (red[4 * tid] + red[4 * tid + 1])
                    + (red[4 * tid + 2] + red[4 * tid + 3]);
            inv[tid] = 1.0f / s;
        }
        __syncthreads();
        // --- context accumulation ---
#pragma unroll 4
        for (int cc = 0; cc < 64; cc++) {
            float ic = inv[cc];
            float wv0 = E[cc * K5_EPAD + bq0] * ic;
            float wv1 = E[cc * K5_EPAD + bq1] * ic;
            ull w0 = pack2(wv0), w1 = pack2(wv1);
            const ulonglong2* hp2 = (const ulonglong2*)(hs + (tile * 64 + cc) * 16);
            ulonglong2 h0 = hp2[0], h1 = hp2[1], h2 = hp2[2], h3 = hp2[3];
            ctxa[0] = fma2_(w0, h0.x, ctxa[0]); ctxa[1] = fma2_(w0, h0.y, ctxa[1]);
            ctxa[2] = fma2_(w0, h1.x, ctxa[2]); ctxa[3] = fma2_(w0, h1.y, ctxa[3]);
            ctxa[4] = fma2_(w0, h2.x, ctxa[4]); ctxa[5] = fma2_(w0, h2.y, ctxa[5]);
            ctxa[6] = fma2_(w0, h3.x, ctxa[6]); ctxa[7] = fma2_(w0, h3.y, ctxa[7]);
            ctxb[0] = fma2_(w1, h0.x, ctxb[0]); ctxb[1] = fma2_(w1, h0.y, ctxb[1]);
            ctxb[2] = fma2_(w1, h1.x, ctxb[2]); ctxb[3] = fma2_(w1, h1.y, ctxb[3]);
            ctxb[4] = fma2_(w1, h2.x, ctxb[4]); ctxb[5] = fma2_(w1, h2.y, ctxb[5]);
            ctxb[6] = fma2_(w1, h3.x, ctxb[6]); ctxb[7] = fma2_(w1, h3.y, ctxb[7]);
        }
        __syncthreads();
    }

    // --- scoring epilogue for both rows ---
#pragma unroll
    for (int half = 0; half < 2; half++) {
        float hr[16], cx[16];
#pragma unroll
        for (int d = 0; d < 8; d++) {
            float2 a = unpk(half ? hrb[d] : hra[d]);
            float2 b = unpk(half ? ctxb[d] : ctxa[d]);
            hr[2 * d] = a.x; hr[2 * d + 1] = a.y;
            cx[2 * d] = b.x; cx[2 * d + 1] = b.y;
        }
        float p = 0.0f;
#pragma unroll
        for (int d = 0; d < 16; d++) {
            float s = 0.0f;
#pragma unroll
            for (int e = 0; e < 16; e++) s = fmaf(hr[e], ws[d * 16 + e], s);
#pragma unroll
            for (int e = 0; e < 16; e++) s = fmaf(cx[e], ws[256 + d * 16 + e], s);
            p = fmaf(tanhf(s), ws[512 + d], p);
        }
        out[(size_t)t * BB + (half ? bq1 : bq0)] = sigmoidf_fast(p);
    }
}

// ---------------------------------------------------------------------------
extern "C" void kernel_launch(void* const* d_in, const int* in_sizes, int n_in,
                              void* d_out, int out_size)
{
    const float* X     = (const float*)d_in[0];
    const float* Wih_f = (const float*)d_in[1];
    const float* Whh_f = (const float*)d_in[2];
    const float* bih_f = (const float*)d_in[3];
    const float* bhh_f = (const float*)d_in[4];
    const float* Wih_b = (const float*)d_in[5];
    const float* Whh_b = (const float*)d_in[6];
    const float* bih_b = (const float*)d_in[7];
    const float* bhh_b = (const float*)d_in[8];
    const float* Wih_p = (const float*)d_in[9];
    const float* Whh_p = (const float*)d_in[10];
    const float* bih_p = (const float*)d_in[11];
    const float* bhh_p = (const float*)d_in[12];
    const float* W_h   = (const float*)d_in[13];
    const float* W_e   = (const float*)d_in[14];
    const float* W_v   = (const float*)d_in[15];
    float* out = (float*)d_out;

    cudaFuncSetAttribute(k5_attn, cudaFuncAttributeMaxDynamicSharedMemorySize,
                         K5_SMEM_BYTES);

    k1_proj<<<512, 128>>>(X, Wih_f, Wih_b, bih_f, bhh_f, bih_b, bhh_b);
    k2_bilstm<<<256, 128>>>(Whh_f, Whh_b);
    k4_ptr<<<128, 128>>>(Wih_p, Whh_p, bih_p, bhh_p);
    k5_attn<<<TT, 256, K5_SMEM_BYTES>>>(W_h, W_e, W_v, out);
}

// round 6
// speedup vs baseline: 1.2854x; 1.2854x over previous
#include <cuda_runtime.h>
#include <cuda_bf16.h>

// Problem constants
#define TT 128
#define BB 512
#define DD 768

typedef unsigned long long ull;

// Scratch (device globals — no runtime allocation allowed)
__device__ float g_G[(size_t)TT * BB * 64];  // gates [t][b][64]: 0-31 fwd, 32-63 bwd (bias included)
__device__ float g_h[(size_t)TT * BB * 16];  // bi-LSTM hidden [t][b][16]
__device__ float g_z[(size_t)TT * BB * 16];  // ptr-LSTM hidden [t][b][16]

__device__ __forceinline__ float sigmoidf_fast(float x) {
    return 1.0f / (1.0f + __expf(-x));
}

// ---- packed f32x2 helpers (used by k5) ----
__device__ __forceinline__ ull fma2_(ull a, ull b, ull c) {
    ull d;
    asm("fma.rn.f32x2 %0, %1, %2, %3;" : "=l"(d) : "l"(a), "l"(b), "l"(c));
    return d;
}
__device__ __forceinline__ ull pack2(float x) {
    ull d;
    asm("mov.b64 %0, {%1, %1};" : "=l"(d) : "f"(x));
    return d;
}
__device__ __forceinline__ float2 unpk(ull v) {
    float lo, hi;
    asm("mov.b64 {%0, %1}, %2;" : "=f"(lo), "=f"(hi) : "l"(v));
    return make_float2(lo, hi);
}

// ---- warp-level MMA helpers (arch-unconditional: sm_80+ PTX) ----
__device__ __forceinline__ unsigned smem_u32(const void* p) {
    unsigned a;
    asm("{ .reg .u64 t; cvta.to.shared.u64 t, %1; cvt.u32.u64 %0, t; }"
        : "=r"(a) : "l"(p));
    return a;
}
__device__ __forceinline__ void mma16816(float* d, const unsigned* a, const unsigned* b) {
    asm volatile(
        "mma.sync.aligned.m16n8k16.row.col.f32.bf16.bf16.f32 "
        "{%0,%1,%2,%3}, {%4,%5,%6,%7}, {%8,%9}, {%0,%1,%2,%3};"
        : "+f"(d[0]), "+f"(d[1]), "+f"(d[2]), "+f"(d[3])
        : "r"(a[0]), "r"(a[1]), "r"(a[2]), "r"(a[3]), "r"(b[0]), "r"(b[1]));
}
__device__ __forceinline__ void ldsm4(unsigned* r, unsigned addr) {
    asm volatile("ldmatrix.sync.aligned.m8n8.x4.shared.b16 {%0,%1,%2,%3}, [%4];"
                 : "=r"(r[0]), "=r"(r[1]), "=r"(r[2]), "=r"(r[3]) : "r"(addr));
}

// fp32 -> bf16 hi/lo split of 8 elements (packed as 4x uint32 each)
__device__ __forceinline__ void cvt_split8(const float* xs, unsigned* hi, unsigned* lo) {
#pragma unroll
    for (int q = 0; q < 4; q++) {
        float a = xs[2 * q], b = xs[2 * q + 1];
        __nv_bfloat162 h2 = __floats2bfloat162_rn(a, b);
        float ra = a - __bfloat162float(h2.x);
        float rb = b - __bfloat162float(h2.y);
        __nv_bfloat162 l2 = __floats2bfloat162_rn(ra, rb);
        hi[q] = *(unsigned*)&h2;
        lo[q] = *(unsigned*)&l2;
    }
}

// ---------------------------------------------------------------------------
// K1 (HMMA): G = X @ Wcat^T + bias via bf16 hi/lo split.
// G ~= Xhi*Whi + Xhi*Wlo + Xlo*Whi (fp32 accumulators; dropped lo*lo ~2^-18).
// 512 blocks x 256 thr. Per block: M=128 rows, N=64 gates, 12 K-chunks of 64.
// fp32 tiles are converted in-kernel into XOR-swizzled bf16 hi/lo smem tiles
// (16B-chunk index ^= row&7 -> conflict-free ldmatrix). Each warp owns one
// 16-row m-tile x all 64 gates: per k-step 2 A-ldsm4 + 8 B-ldsm4 + 24 MMA.
// ---------------------------------------------------------------------------
#define K1_XHI  0
#define K1_XLO  16384
#define K1_WHI  32768
#define K1_WLO  (32768 + 8192)
#define K1_BIAS (32768 + 16384)
#define K1_SMEM_TOTAL (K1_BIAS + 256)

extern __shared__ char k1s[];

__global__ __launch_bounds__(256) void k1_proj_mma(
    const float* __restrict__ X,
    const float* __restrict__ Wf, const float* __restrict__ Wb,
    const float* __restrict__ bf1, const float* __restrict__ bf2,
    const float* __restrict__ bb1, const float* __restrict__ bb2)
{
    const int tid  = threadIdx.x;
    const int wid  = tid >> 5;
    const int lane = tid & 31;
    const int r0   = blockIdx.x * 128;
    const unsigned sb = smem_u32(k1s);

    float* bias = (float*)(k1s + K1_BIAS);
    if (tid < 64)
        bias[tid] = (tid < 32) ? (bf1[tid] + bf2[tid])
                               : (bb1[tid - 32] + bb2[tid - 32]);

    const int arow = tid >> 3;   // 0..31
    const int acg  = tid & 7;    // 16B chunk within 64-col tile

    // ldmatrix lane-address selectors
    const int qr = lane & 7;
    const int hm = (lane >> 3) & 1;
    const int hk = lane >> 4;

    float acc[8][4];
#pragma unroll
    for (int n = 0; n < 8; n++)
#pragma unroll
        for (int i = 0; i < 4; i++) acc[n][i] = 0.0f;

    for (int c = 0; c < 12; c++) {
        if (c) __syncthreads();   // previous chunk's MMA reads done
        // ---- X tile: 128 rows x 64 cols -> bf16 hi/lo, swizzled ----
#pragma unroll
        for (int sub = 0; sub < 4; sub++) {
            int row = sub * 32 + arow;
            const float* p = X + (size_t)(r0 + row) * DD + c * 64 + acg * 8;
            float xs[8];
            *(float4*)&xs[0] = *(const float4*)p;
            *(float4*)&xs[4] = *(const float4*)(p + 4);
            unsigned hi[4], lo[4];
            cvt_split8(xs, hi, lo);
            unsigned off = (unsigned)row * 128 + (unsigned)(acg ^ (row & 7)) * 16;
            *(uint4*)(k1s + K1_XHI + off) = make_uint4(hi[0], hi[1], hi[2], hi[3]);
            *(uint4*)(k1s + K1_XLO + off) = make_uint4(lo[0], lo[1], lo[2], lo[3]);
        }
        // ---- W tile: 64 gate rows x 64 cols ----
#pragma unroll
        for (int sub = 0; sub < 2; sub++) {
            int row = sub * 32 + arow;
            const float* p = ((row < 32) ? (Wf + (size_t)row * DD)
                                         : (Wb + (size_t)(row - 32) * DD))
                             + c * 64 + acg * 8;
            float xs[8];
            *(float4*)&xs[0] = *(const float4*)p;
            *(float4*)&xs[4] = *(const float4*)(p + 4);
            unsigned hi[4], lo[4];
            cvt_split8(xs, hi, lo);
            unsigned off = (unsigned)row * 128 + (unsigned)(acg ^ (row & 7)) * 16;
            *(uint4*)(k1s + K1_WHI + off) = make_uint4(hi[0], hi[1], hi[2], hi[3]);
            *(uint4*)(k1s + K1_WLO + off) = make_uint4(lo[0], lo[1], lo[2], lo[3]);
        }
        __syncthreads();

        // ---- MMA: 4 k-steps of 16 ----
#pragma unroll
        for (int ks = 0; ks < 4; ks++) {
            // A fragment addresses: matrices [rows0-7,k0-7][rows8-15,k0-7]
            //                                [rows0-7,k8-15][rows8-15,k8-15]
            int ar = wid * 16 + hm * 8 + qr;
            unsigned ac = (unsigned)((2 * ks + hk) ^ (ar & 7));
            unsigned aoff = (unsigned)ar * 128 + ac * 16;
            unsigned ahi[4], alo[4];
            ldsm4(ahi, sb + K1_XHI + aoff);
            ldsm4(alo, sb + K1_XLO + aoff);
#pragma unroll
            for (int p = 0; p < 4; p++) {
                // B matrices: [g0-7,k0-7][g0-7,k8-15][g8-15,k0-7][g8-15,k8-15]
                int g = p * 16 + hk * 8 + qr;
                unsigned bc = (unsigned)((2 * ks + hm) ^ (g & 7));
                unsigned boff = (unsigned)g * 128 + bc * 16;
                unsigned bhi[4], blo[4];
                ldsm4(bhi, sb + K1_WHI + boff);
                ldsm4(blo, sb + K1_WLO + boff);
                mma16816(acc[2 * p],     ahi, bhi);
                mma16816(acc[2 * p],     ahi, blo);
                mma16816(acc[2 * p],     alo, bhi);
                mma16816(acc[2 * p + 1], ahi, bhi + 2);
                mma16816(acc[2 * p + 1], ahi, blo + 2);
                mma16816(acc[2 * p + 1], alo, bhi + 2);
            }
        }
    }

    // ---- epilogue: D fragments -> g_G with bias ----
    const int mrow = r0 + wid * 16 + (lane >> 2);
    const int cb   = (lane & 3) * 2;
#pragma unroll
    for (int nt = 0; nt < 8; nt++) {
        int col = nt * 8 + cb;
        float b0 = bias[col], b1 = bias[col + 1];
        *(float2*)(g_G + (size_t)mrow * 64 + col) =
            make_float2(acc[nt][0] + b0, acc[nt][1] + b1);
        *(float2*)(g_G + (size_t)(mrow + 8) * 64 + col) =
            make_float2(acc[nt][2] + b0, acc[nt][3] + b1);
    }
}

// ---------------------------------------------------------------------------
// K2: bi-LSTM scans (fwd + bwd), one warp per (batch item, direction).
// ---------------------------------------------------------------------------
__global__ __launch_bounds__(128) void k2_bilstm(
    const float* __restrict__ Whhf, const float* __restrict__ Whhb)
{
    const unsigned FULL = 0xffffffffu;
    int warp = blockIdx.x * (blockDim.x >> 5) + (threadIdx.x >> 5); // 0..1023
    int lane = threadIdx.x & 31;
    int dir  = warp >> 9;
    int b    = warp & 511;

    const float* Whh = dir ? Whhb : Whhf;
    float w[8];
#pragma unroll
    for (int k = 0; k < 8; k++) w[k] = Whh[lane * 8 + k];

    float hrep[8];
#pragma unroll
    for (int k = 0; k < 8; k++) hrep[k] = 0.0f;
    float c = 0.0f;

    const int coloff = dir * 32 + lane;
    int t0 = dir ? (TT - 1) : 0;
    float gcur = g_G[((size_t)t0 * BB + b) * 64 + coloff];

    for (int s = 0; s < TT; s++) {
        int t = dir ? (TT - 1 - s) : s;
        float gnext = 0.0f;
        if (s + 1 < TT) {
            int tn = dir ? (TT - 2 - s) : (s + 1);
            gnext = g_G[((size_t)tn * BB + b) * 64 + coloff];
        }
        float gate = gcur;
#pragma unroll
        for (int k = 0; k < 8; k++) gate = fmaf(hrep[k], w[k], gate);

        float a = (lane >= 16 && lane < 24) ? tanhf(gate) : sigmoidf_fast(gate);
        float fv = __shfl_sync(FULL, a, lane + 8);
        float gv = __shfl_sync(FULL, a, lane + 16);
        float ov = __shfl_sync(FULL, a, lane + 24);

        float hnew = 0.0f;
        if (lane < 8) {
            c = fmaf(fv, c, a * gv);
            hnew = ov * tanhf(c);
            g_h[((size_t)t * BB + b) * 16 + dir * 8 + lane] = hnew;
        }
#pragma unroll
        for (int k = 0; k < 8; k++) hrep[k] = __shfl_sync(FULL, hnew, k);
        gcur = gnext;
    }
}

// ---------------------------------------------------------------------------
// K4: ptr-LSTM scan, one warp per batch item.
// ---------------------------------------------------------------------------
__global__ __launch_bounds__(128) void k4_ptr(
    const float* __restrict__ Wih, const float* __restrict__ Whh,
    const float* __restrict__ b1, const float* __restrict__ b2)
{
    const unsigned FULL = 0xffffffffu;
    int warp = blockIdx.x * (blockDim.x >> 5) + (threadIdx.x >> 5); // 0..511
    int lane = threadIdx.x & 31;
    int b    = warp;

    const int r0 = lane, r1 = lane + 32;
    float wi0[16], wi1[16], wh0[16], wh1[16];
#pragma unroll
    for (int k = 0; k < 16; k++) {
        wi0[k] = Wih[r0 * 16 + k];
        wi1[k] = Wih[r1 * 16 + k];
        wh0[k] = Whh[r0 * 16 + k];
        wh1[k] = Whh[r1 * 16 + k];
    }
    const float bias0 = b1[r0] + b2[r0];
    const float bias1 = b1[r1] + b2[r1];

    float zrep[16];
#pragma unroll
    for (int k = 0; k < 16; k++) zrep[k] = 0.0f;
    float c = 0.0f;

    const float4* hp = (const float4*)g_h;
    size_t base = ((size_t)0 * BB + b) * 4;
    float4 x0 = hp[base + 0], x1 = hp[base + 1], x2 = hp[base + 2], x3 = hp[base + 3];

    for (int t = 0; t < TT; t++) {
        float4 n0 = x0, n1 = x1, n2 = x2, n3 = x3;
        if (t + 1 < TT) {
            size_t nb = ((size_t)(t + 1) * BB + b) * 4;
            n0 = hp[nb + 0]; n1 = hp[nb + 1]; n2 = hp[nb + 2]; n3 = hp[nb + 3];
        }
        float xin[16] = {x0.x, x0.y, x0.z, x0.w, x1.x, x1.y, x1.z, x1.w,
                         x2.x, x2.y, x2.z, x2.w, x3.x, x3.y, x3.z, x3.w};
        float u0 = bias0, u1 = bias1;
#pragma unroll
        for (int k = 0; k < 16; k++) {
            u0 = fmaf(xin[k], wi0[k], u0);
            u1 = fmaf(xin[k], wi1[k], u1);
        }
#pragma unroll
        for (int k = 0; k < 16; k++) {
            u0 = fmaf(zrep[k], wh0[k], u0);
            u1 = fmaf(zrep[k], wh1[k], u1);
        }
        float a0 = sigmoidf_fast(u0);
        float a1 = (lane < 16) ? tanhf(u1) : sigmoidf_fast(u1);
        float fv = __shfl_sync(FULL, a0, lane + 16);
        float ov = __shfl_sync(FULL, a1, lane + 16);

        float zn = 0.0f;
        if (lane < 16) {
            c = fmaf(fv, c, a0 * a1);
            zn = ov * tanhf(c);
            g_z[((size_t)t * BB + b) * 16 + lane] = zn;
        }
#pragma unroll
        for (int k = 0; k < 16; k++) zrep[k] = __shfl_sync(FULL, zn, k);
        x0 = n0; x1 = n1; x2 = n2; x3 = n3;
    }
}

// ---------------------------------------------------------------------------
// K5: per-timestep attention + scoring. One block per t, 256 threads,
// each thread owns 2 query rows (bq, bq+256). Scores bounded (|S|<=16):
// no max pass. E stride 516 -> colsum banks = lane id (conflict-free).
// ---------------------------------------------------------------------------
#define K5_EPAD 516
#define K5_SMEM_FLOATS (8192 + 8192 + 64 * K5_EPAD + 256 + 64 + 528)
#define K5_SMEM_BYTES  (K5_SMEM_FLOATS * 4)

extern __shared__ float k5_smem[];

__global__ __launch_bounds__(256, 1) void k5_attn(
    const float* __restrict__ Wh, const float* __restrict__ We,
    const float* __restrict__ Wv, float* __restrict__ out)
{
    float* hs  = k5_smem;                  // 512*16
    float* zs  = hs + 8192;                // 512*16
    float* E   = zs + 8192;                // 64 * 516
    float* red = E + 64 * K5_EPAD;         // 256
    float* inv = red + 256;                // 64
    float* ws  = inv + 64;                 // Wh[256] | We[256] | Wv[16]

    const int tid = threadIdx.x;
    const int t   = blockIdx.x;

    const float4* hg = (const float4*)(g_h + (size_t)t * BB * 16);
    const float4* zg = (const float4*)(g_z + (size_t)t * BB * 16);
    float4* hs4 = (float4*)hs;
    float4* zs4 = (float4*)zs;
#pragma unroll
    for (int i = 0; i < 8; i++) {
        hs4[i * 256 + tid] = hg[i * 256 + tid];
        zs4[i * 256 + tid] = zg[i * 256 + tid];
    }
    ws[tid]       = Wh[tid];
    ws[256 + tid] = We[tid];
    if (tid < 16) ws[512 + tid] = Wv[tid];
    __syncthreads();

    const int bq0 = tid;
    const int bq1 = tid + 256;
    ull hra[8], hrb[8];
    {
        const ulonglong2* ha = (const ulonglong2*)(hs + bq0 * 16);
        const ulonglong2* hb = (const ulonglong2*)(hs + bq1 * 16);
#pragma unroll
        for (int i = 0; i < 4; i++) {
            ulonglong2 va = ha[i], vb = hb[i];
            hra[2 * i] = va.x; hra[2 * i + 1] = va.y;
            hrb[2 * i] = vb.x; hrb[2 * i + 1] = vb.y;
        }
    }
    ull ctxa[8], ctxb[8];
#pragma unroll
    for (int d = 0; d < 8; d++) { ctxa[d] = 0ull; ctxb[d] = 0ull; }

    for (int tile = 0; tile < 8; tile++) {
        // --- scores + exp for 64 softmax-columns, 2 query rows/thread ---
#pragma unroll 4
        for (int cc = 0; cc < 64; cc++) {
            const ulonglong2* zp = (const ulonglong2*)(zs + (tile * 64 + cc) * 16);
            ulonglong2 z0 = zp[0], z1 = zp[1], z2 = zp[2], z3 = zp[3];
            ull da0 = 0ull, da1 = 0ull, db0 = 0ull, db1 = 0ull;
            da0 = fma2_(hra[0], z0.x, da0); da1 = fma2_(hra[1], z0.y, da1);
            da0 = fma2_(hra[2], z1.x, da0); da1 = fma2_(hra[3], z1.y, da1);
            da0 = fma2_(hra[4], z2.x, da0); da1 = fma2_(hra[5], z2.y, da1);
            da0 = fma2_(hra[6], z3.x, da0); da1 = fma2_(hra[7], z3.y, da1);
            db0 = fma2_(hrb[0], z0.x, db0); db1 = fma2_(hrb[1], z0.y, db1);
            db0 = fma2_(hrb[2], z1.x, db0); db1 = fma2_(hrb[3], z1.y, db1);
            db0 = fma2_(hrb[4], z2.x, db0); db1 = fma2_(hrb[5], z2.y, db1);
            db0 = fma2_(hrb[6], z3.x, db0); db1 = fma2_(hrb[7], z3.y, db1);
            float2 a0 = unpk(da0), a1 = unpk(da1);
            float2 b0 = unpk(db0), b1 = unpk(db1);
            E[cc * K5_EPAD + bq0] = __expf((a0.x + a0.y) + (a1.x + a1.y));
            E[cc * K5_EPAD + bq1] = __expf((b0.x + b0.y) + (b1.x + b1.y));
        }
        __syncthreads();
        // --- column sums (over b): bank = lane, conflict-free ---
        {
            int cc = tid >> 2, seg = tid & 3;
            float s0 = 0.0f, s1 = 0.0f, s2 = 0.0f, s3 = 0.0f;
            const float* ep = E + cc * K5_EPAD + seg;
#pragma unroll 8
            for (int j = 0; j < 32; j++) {
                s0 += ep[16 * j + 0];
                s1 += ep[16 * j + 4];
                s2 += ep[16 * j + 8];
                s3 += ep[16 * j + 12];
            }
            red[tid] = (s0 + s1) + (s2 + s3);
        }
        __syncthreads();
        if (tid < 64) {
            float s = (red[4 * tid] + red[4 * tid + 1])
                    + (red[4 * tid + 2] + red[4 * tid + 3]);
            inv[tid] = 1.0f / s;
        }
        __syncthreads();
        // --- context accumulation ---
#pragma unroll 4
        for (int cc = 0; cc < 64; cc++) {
            float ic = inv[cc];
            float wv0 = E[cc * K5_EPAD + bq0] * ic;
            float wv1 = E[cc * K5_EPAD + bq1] * ic;
            ull w0 = pack2(wv0), w1 = pack2(wv1);
            const ulonglong2* hp2 = (const ulonglong2*)(hs + (tile * 64 + cc) * 16);
            ulonglong2 h0 = hp2[0], h1 = hp2[1], h2 = hp2[2], h3 = hp2[3];
            ctxa[0] = fma2_(w0, h0.x, ctxa[0]); ctxa[1] = fma2_(w0, h0.y, ctxa[1]);
            ctxa[2] = fma2_(w0, h1.x, ctxa[2]); ctxa[3] = fma2_(w0, h1.y, ctxa[3]);
            ctxa[4] = fma2_(w0, h2.x, ctxa[4]); ctxa[5] = fma2_(w0, h2.y, ctxa[5]);
            ctxa[6] = fma2_(w0, h3.x, ctxa[6]); ctxa[7] = fma2_(w0, h3.y, ctxa[7]);
            ctxb[0] = fma2_(w1, h0.x, ctxb[0]); ctxb[1] = fma2_(w1, h0.y, ctxb[1]);
            ctxb[2] = fma2_(w1, h1.x, ctxb[2]); ctxb[3] = fma2_(w1, h1.y, ctxb[3]);
            ctxb[4] = fma2_(w1, h2.x, ctxb[4]); ctxb[5] = fma2_(w1, h2.y, ctxb[5]);
            ctxb[6] = fma2_(w1, h3.x, ctxb[6]); ctxb[7] = fma2_(w1, h3.y, ctxb[7]);
        }
        __syncthreads();
    }

    // --- scoring epilogue for both rows ---
#pragma unroll
    for (int half = 0; half < 2; half++) {
        float hr[16], cx[16];
#pragma unroll
        for (int d = 0; d < 8; d++) {
            float2 a = unpk(half ? hrb[d] : hra[d]);
            float2 b = unpk(half ? ctxb[d] : ctxa[d]);
            hr[2 * d] = a.x; hr[2 * d + 1] = a.y;
            cx[2 * d] = b.x; cx[2 * d + 1] = b.y;
        }
        float p = 0.0f;
#pragma unroll
        for (int d = 0; d < 16; d++) {
            float s = 0.0f;
#pragma unroll
            for (int e = 0; e < 16; e++) s = fmaf(hr[e], ws[d * 16 + e], s);
#pragma unroll
            for (int e = 0; e < 16; e++) s = fmaf(cx[e], ws[256 + d * 16 + e], s);
            p = fmaf(tanhf(s), ws[512 + d], p);
        }
        out[(size_t)t * BB + (half ? bq1 : bq0)] = sigmoidf_fast(p);
    }
}

// ---------------------------------------------------------------------------
extern "C" void kernel_launch(void* const* d_in, const int* in_sizes, int n_in,
                              void* d_out, int out_size)
{
    const float* X     = (const float*)d_in[0];
    const float* Wih_f = (const float*)d_in[1];
    const float* Whh_f = (const float*)d_in[2];
    const float* bih_f = (const float*)d_in[3];
    const float* bhh_f = (const float*)d_in[4];
    const float* Wih_b = (const float*)d_in[5];
    const float* Whh_b = (const float*)d_in[6];
    const float* bih_b = (const float*)d_in[7];
    const float* bhh_b = (const float*)d_in[8];
    const float* Wih_p = (const float*)d_in[9];
    const float* Whh_p = (const float*)d_in[10];
    const float* bih_p = (const float*)d_in[11];
    const float* bhh_p = (const float*)d_in[12];
    const float* W_h   = (const float*)d_in[13];
    const float* W_e   = (const float*)d_in[14];
    const float* W_v   = (const float*)d_in[15];
    float* out = (float*)d_out;

    cudaFuncSetAttribute(k1_proj_mma, cudaFuncAttributeMaxDynamicSharedMemorySize,
                         K1_SMEM_TOTAL);
    cudaFuncSetAttribute(k5_attn, cudaFuncAttributeMaxDynamicSharedMemorySize,
                         K5_SMEM_BYTES);

    k1_proj_mma<<<512, 256, K1_SMEM_TOTAL>>>(X, Wih_f, Wih_b,
                                             bih_f, bhh_f, bih_b, bhh_b);
    k2_bilstm<<<256, 128>>>(Whh_f, Whh_b);
    k4_ptr<<<128, 128>>>(Wih_p, Whh_p, bih_p, bhh_p);
    k5_attn<<<TT, 256, K5_SMEM_BYTES>>>(W_h, W_e, W_v, out);
}

// round 7
// speedup vs baseline: 1.5228x; 1.1847x over previous
#include <cuda_runtime.h>
#include <cuda_bf16.h>
#include <cuda_fp16.h>

// Problem constants
#define TT 128
#define BB 512
#define DD 768

typedef unsigned long long ull;

// Scratch (device globals — no runtime allocation allowed)
__device__ float g_G[(size_t)TT * BB * 64];  // gates [t][b][64]: 0-31 fwd, 32-63 bwd (bias included)
__device__ float g_h[(size_t)TT * BB * 16];  // bi-LSTM hidden [t][b][16]
__device__ float g_z[(size_t)TT * BB * 16];  // ptr-LSTM hidden [t][b][16]

__device__ __forceinline__ float sigmoidf_fast(float x) {
    return 1.0f / (1.0f + __expf(-x));
}

// ---- packed f32x2 helpers (used by k5) ----
__device__ __forceinline__ ull fma2_(ull a, ull b, ull c) {
    ull d;
    asm("fma.rn.f32x2 %0, %1, %2, %3;" : "=l"(d) : "l"(a), "l"(b), "l"(c));
    return d;
}
__device__ __forceinline__ ull pack2(float x) {
    ull d;
    asm("mov.b64 %0, {%1, %1};" : "=l"(d) : "f"(x));
    return d;
}
__device__ __forceinline__ float2 unpk(ull v) {
    float lo, hi;
    asm("mov.b64 {%0, %1}, %2;" : "=f"(lo), "=f"(hi) : "l"(v));
    return make_float2(lo, hi);
}

// ---- warp-level MMA helpers (arch-unconditional: sm_80+ PTX) ----
__device__ __forceinline__ unsigned smem_u32(const void* p) {
    unsigned a;
    asm("{ .reg .u64 t; cvta.to.shared.u64 t, %1; cvt.u32.u64 %0, t; }"
        : "=r"(a) : "l"(p));
    return a;
}
__device__ __forceinline__ void mma16816h(float* d, const unsigned* a, const unsigned* b) {
    asm volatile(
        "mma.sync.aligned.m16n8k16.row.col.f32.f16.f16.f32 "
        "{%0,%1,%2,%3}, {%4,%5,%6,%7}, {%8,%9}, {%0,%1,%2,%3};"
        : "+f"(d[0]), "+f"(d[1]), "+f"(d[2]), "+f"(d[3])
        : "r"(a[0]), "r"(a[1]), "r"(a[2]), "r"(a[3]), "r"(b[0]), "r"(b[1]));
}
__device__ __forceinline__ void ldsm4(unsigned* r, unsigned addr) {
    asm volatile("ldmatrix.sync.aligned.m8n8.x4.shared.b16 {%0,%1,%2,%3}, [%4];"
                 : "=r"(r[0]), "=r"(r[1]), "=r"(r[2]), "=r"(r[3]) : "r"(addr));
}

// ---------------------------------------------------------------------------
// K1 (HMMA, fp16 2-product): G = X @ Wcat^T + bias.
// x16 = fp16(x); Whi = fp16(w); Wlo = fp16(w - Whi).
// G ~= x16*Whi + x16*Wlo  (residual (x-x16)*w -> gate rel err ~2e-4,
// damped ~10x downstream -> output err ~1e-5, tolerance 1e-3).
// 512 blocks x 256 thr, BM=128, N=64, 12 K-chunks of 64.
// Double-buffered smem tiles, ONE syncthreads per chunk, LDG prefetch of
// chunk c+1 issued before the MMA phase (hidden under HMMA).
// Swizzle: 16B-chunk index ^= row&7 -> conflict-free ldmatrix.
// ---------------------------------------------------------------------------
#define K1_X16  0                       // 2 x 128x64 fp16 = 2 x 16KB
#define K1_WHI  (2 * 16384)             // 2 x 64x64 fp16 = 2 x 8KB
#define K1_WLO  (K1_WHI + 2 * 8192)     // 2 x 8KB
#define K1_BIAS (K1_WLO + 2 * 8192)
#define K1_SMEM_TOTAL (K1_BIAS + 256)

extern __shared__ char k1s[];

__global__ __launch_bounds__(256) void k1_proj_mma(
    const float* __restrict__ X,
    const float* __restrict__ Wf, const float* __restrict__ Wb,
    const float* __restrict__ bf1, const float* __restrict__ bf2,
    const float* __restrict__ bb1, const float* __restrict__ bb2)
{
    const int tid  = threadIdx.x;
    const int wid  = tid >> 5;
    const int lane = tid & 31;
    const int r0   = blockIdx.x * 128;
    const unsigned sb = smem_u32(k1s);

    float* bias = (float*)(k1s + K1_BIAS);
    if (tid < 64)
        bias[tid] = (tid < 32) ? (bf1[tid] + bf2[tid])
                               : (bb1[tid - 32] + bb2[tid - 32]);

    const int arow = tid >> 3;   // 0..31
    const int acg  = tid & 7;    // 16B chunk within 64-col tile

    // ldmatrix lane-address selectors
    const int qr = lane & 7;
    const int hm = (lane >> 3) & 1;
    const int hk = lane >> 4;

    // W row pointer for the loader role (gate row = arow + 32*sub)
    const float* xrows[4];
    const float* wrows[2];
#pragma unroll
    for (int sub = 0; sub < 4; sub++)
        xrows[sub] = X + (size_t)(r0 + sub * 32 + arow) * DD + acg * 8;
#pragma unroll
    for (int sub = 0; sub < 2; sub++) {
        int row = sub * 32 + arow;
        wrows[sub] = ((row < 32) ? (Wf + (size_t)row * DD)
                                 : (Wb + (size_t)(row - 32) * DD)) + acg * 8;
    }

    float acc[8][4];
#pragma unroll
    for (int n = 0; n < 8; n++)
#pragma unroll
        for (int i = 0; i < 4; i++) acc[n][i] = 0.0f;

    // prefetch chunk 0 into registers
    float4 xp[4][2], wp[2][2];
#pragma unroll
    for (int sub = 0; sub < 4; sub++) {
        xp[sub][0] = *(const float4*)(xrows[sub] + 0);
        xp[sub][1] = *(const float4*)(xrows[sub] + 4);
    }
#pragma unroll
    for (int sub = 0; sub < 2; sub++) {
        wp[sub][0] = *(const float4*)(wrows[sub] + 0);
        wp[sub][1] = *(const float4*)(wrows[sub] + 4);
    }

    for (int c = 0; c < 12; c++) {
        const int p = c & 1;
        char* xbuf = k1s + K1_X16 + p * 16384;
        char* hbuf = k1s + K1_WHI + p * 8192;
        char* lbuf = k1s + K1_WLO + p * 8192;

        // ---- convert prefetched regs -> fp16 tiles (swizzled) ----
#pragma unroll
        for (int sub = 0; sub < 4; sub++) {
            float xs[8];
            *(float4*)&xs[0] = xp[sub][0];
            *(float4*)&xs[4] = xp[sub][1];
            unsigned hv[4];
#pragma unroll
            for (int q = 0; q < 4; q++) {
                __half2 h2 = __floats2half2_rn(xs[2 * q], xs[2 * q + 1]);
                hv[q] = *(unsigned*)&h2;
            }
            int row = sub * 32 + arow;
            unsigned off = (unsigned)row * 128 + (unsigned)(acg ^ (row & 7)) * 16;
            *(uint4*)(xbuf + off) = make_uint4(hv[0], hv[1], hv[2], hv[3]);
        }
#pragma unroll
        for (int sub = 0; sub < 2; sub++) {
            float xs[8];
            *(float4*)&xs[0] = wp[sub][0];
            *(float4*)&xs[4] = wp[sub][1];
            unsigned hv[4], lv[4];
#pragma unroll
            for (int q = 0; q < 4; q++) {
                float a = xs[2 * q], b = xs[2 * q + 1];
                __half2 h2 = __floats2half2_rn(a, b);
                float ra = a - __half2float(__low2half(h2));
                float rb = b - __half2float(__high2half(h2));
                __half2 l2 = __floats2half2_rn(ra, rb);
                hv[q] = *(unsigned*)&h2;
                lv[q] = *(unsigned*)&l2;
            }
            int row = sub * 32 + arow;
            unsigned off = (unsigned)row * 128 + (unsigned)(acg ^ (row & 7)) * 16;
            *(uint4*)(hbuf + off) = make_uint4(hv[0], hv[1], hv[2], hv[3]);
            *(uint4*)(lbuf + off) = make_uint4(lv[0], lv[1], lv[2], lv[3]);
        }
        __syncthreads();   // tiles visible; prior MMA on this buffer long done

        // ---- prefetch chunk c+1 (consumed next iteration; hidden under MMA) ----
        if (c + 1 < 12) {
            const int kn = (c + 1) * 64;
#pragma unroll
            for (int sub = 0; sub < 4; sub++) {
                xp[sub][0] = *(const float4*)(xrows[sub] + kn);
                xp[sub][1] = *(const float4*)(xrows[sub] + kn + 4);
            }
#pragma unroll
            for (int sub = 0; sub < 2; sub++) {
                wp[sub][0] = *(const float4*)(wrows[sub] + kn);
                wp[sub][1] = *(const float4*)(wrows[sub] + kn + 4);
            }
        }

        // ---- MMA: 4 k-steps of 16 ----
        const unsigned xb = sb + K1_X16 + p * 16384;
        const unsigned hb = sb + K1_WHI + p * 8192;
        const unsigned lb = sb + K1_WLO + p * 8192;
#pragma unroll
        for (int ks = 0; ks < 4; ks++) {
            int ar = wid * 16 + hm * 8 + qr;
            unsigned ac = (unsigned)((2 * ks + hk) ^ (ar & 7));
            unsigned aoff = (unsigned)ar * 128 + ac * 16;
            unsigned ax[4];
            ldsm4(ax, xb + aoff);
#pragma unroll
            for (int pp = 0; pp < 4; pp++) {
                int g = pp * 16 + hk * 8 + qr;
                unsigned bc = (unsigned)((2 * ks + hm) ^ (g & 7));
                unsigned boff = (unsigned)g * 128 + bc * 16;
                unsigned bhi[4], blo[4];
                ldsm4(bhi, hb + boff);
                ldsm4(blo, lb + boff);
                mma16816h(acc[2 * pp],     ax, bhi);
                mma16816h(acc[2 * pp],     ax, blo);
                mma16816h(acc[2 * pp + 1], ax, bhi + 2);
                mma16816h(acc[2 * pp + 1], ax, blo + 2);
            }
        }
        // no second sync: next iteration writes the OTHER buffer; writes to
        // this buffer happen after the next sync, by which time all warps
        // have finished this MMA phase.
    }

    // ---- epilogue: D fragments -> g_G with bias ----
    const int mrow = r0 + wid * 16 + (lane >> 2);
    const int cb   = (lane & 3) * 2;
#pragma unroll
    for (int nt = 0; nt < 8; nt++) {
        int col = nt * 8 + cb;
        float b0 = bias[col], b1 = bias[col + 1];
        *(float2*)(g_G + (size_t)mrow * 64 + col) =
            make_float2(acc[nt][0] + b0, acc[nt][1] + b1);
        *(float2*)(g_G + (size_t)(mrow + 8) * 64 + col) =
            make_float2(acc[nt][2] + b0, acc[nt][3] + b1);
    }
}

// ---------------------------------------------------------------------------
// K2: bi-LSTM scans (fwd + bwd), one warp per (batch item, direction).
// ---------------------------------------------------------------------------
__global__ __launch_bounds__(128) void k2_bilstm(
    const float* __restrict__ Whhf, const float* __restrict__ Whhb)
{
    const unsigned FULL = 0xffffffffu;
    int warp = blockIdx.x * (blockDim.x >> 5) + (threadIdx.x >> 5); // 0..1023
    int lane = threadIdx.x & 31;
    int dir  = warp >> 9;
    int b    = warp & 511;

    const float* Whh = dir ? Whhb : Whhf;
    float w[8];
#pragma unroll
    for (int k = 0; k < 8; k++) w[k] = Whh[lane * 8 + k];

    float hrep[8];
#pragma unroll
    for (int k = 0; k < 8; k++) hrep[k] = 0.0f;
    float c = 0.0f;

    const int coloff = dir * 32 + lane;
    int t0 = dir ? (TT - 1) : 0;
    float gcur = g_G[((size_t)t0 * BB + b) * 64 + coloff];

    for (int s = 0; s < TT; s++) {
        int t = dir ? (TT - 1 - s) : s;
        float gnext = 0.0f;
        if (s + 1 < TT) {
            int tn = dir ? (TT - 2 - s) : (s + 1);
            gnext = g_G[((size_t)tn * BB + b) * 64 + coloff];
        }
        float gate = gcur;
#pragma unroll
        for (int k = 0; k < 8; k++) gate = fmaf(hrep[k], w[k], gate);

        float a = (lane >= 16 && lane < 24) ? tanhf(gate) : sigmoidf_fast(gate);
        float fv = __shfl_sync(FULL, a, lane + 8);
        float gv = __shfl_sync(FULL, a, lane + 16);
        float ov = __shfl_sync(FULL, a, lane + 24);

        float hnew = 0.0f;
        if (lane < 8) {
            c = fmaf(fv, c, a * gv);
            hnew = ov * tanhf(c);
            g_h[((size_t)t * BB + b) * 16 + dir * 8 + lane] = hnew;
        }
#pragma unroll
        for (int k = 0; k < 8; k++) hrep[k] = __shfl_sync(FULL, hnew, k);
        gcur = gnext;
    }
}

// ---------------------------------------------------------------------------
// K4: ptr-LSTM scan, one warp per batch item.
// ---------------------------------------------------------------------------
__global__ __launch_bounds__(128) void k4_ptr(
    const float* __restrict__ Wih, const float* __restrict__ Whh,
    const float* __restrict__ b1, const float* __restrict__ b2)
{
    const unsigned FULL = 0xffffffffu;
    int warp = blockIdx.x * (blockDim.x >> 5) + (threadIdx.x >> 5); // 0..511
    int lane = threadIdx.x & 31;
    int b    = warp;

    const int r0 = lane, r1 = lane + 32;
    float wi0[16], wi1[16], wh0[16], wh1[16];
#pragma unroll
    for (int k = 0; k < 16; k++) {
        wi0[k] = Wih[r0 * 16 + k];
        wi1[k] = Wih[r1 * 16 + k];
        wh0[k] = Whh[r0 * 16 + k];
        wh1[k] = Whh[r1 * 16 + k];
    }
    const float bias0 = b1[r0] + b2[r0];
    const float bias1 = b1[r1] + b2[r1];

    float zrep[16];
#pragma unroll
    for (int k = 0; k < 16; k++) zrep[k] = 0.0f;
    float c = 0.0f;

    const float4* hp = (const float4*)g_h;
    size_t base = ((size_t)0 * BB + b) * 4;
    float4 x0 = hp[base + 0], x1 = hp[base + 1], x2 = hp[base + 2], x3 = hp[base + 3];

    for (int t = 0; t < TT; t++) {
        float4 n0 = x0, n1 = x1, n2 = x2, n3 = x3;
        if (t + 1 < TT) {
            size_t nb = ((size_t)(t + 1) * BB + b) * 4;
            n0 = hp[nb + 0]; n1 = hp[nb + 1]; n2 = hp[nb + 2]; n3 = hp[nb + 3];
        }
        float xin[16] = {x0.x, x0.y, x0.z, x0.w, x1.x, x1.y, x1.z, x1.w,
                         x2.x, x2.y, x2.z, x2.w, x3.x, x3.y, x3.z, x3.w};
        float u0 = bias0, u1 = bias1;
#pragma unroll
        for (int k = 0; k < 16; k++) {
            u0 = fmaf(xin[k], wi0[k], u0);
            u1 = fmaf(xin[k], wi1[k], u1);
        }
#pragma unroll
        for (int k = 0; k < 16; k++) {
            u0 = fmaf(zrep[k], wh0[k], u0);
            u1 = fmaf(zrep[k], wh1[k], u1);
        }
        float a0 = sigmoidf_fast(u0);
        float a1 = (lane < 16) ? tanhf(u1) : sigmoidf_fast(u1);
        float fv = __shfl_sync(FULL, a0, lane + 16);
        float ov = __shfl_sync(FULL, a1, lane + 16);

        float zn = 0.0f;
        if (lane < 16) {
            c = fmaf(fv, c, a0 * a1);
            zn = ov * tanhf(c);
            g_z[((size_t)t * BB + b) * 16 + lane] = zn;
        }
#pragma unroll
        for (int k = 0; k < 16; k++) zrep[k] = __shfl_sync(FULL, zn, k);
        x0 = n0; x1 = n1; x2 = n2; x3 = n3;
    }
}

// ---------------------------------------------------------------------------
// K5: per-timestep attention + scoring. One block per t, 256 threads,
// each thread owns 2 query rows (bq, bq+256). Scores bounded (|S|<=16):
// no max pass. E stride 516 -> colsum banks = lane id (conflict-free).
// ---------------------------------------------------------------------------
#define K5_EPAD 516
#define K5_SMEM_FLOATS (8192 + 8192 + 64 * K5_EPAD + 256 + 64 + 528)
#define K5_SMEM_BYTES  (K5_SMEM_FLOATS * 4)

extern __shared__ float k5_smem[];

__global__ __launch_bounds__(256, 1) void k5_attn(
    const float* __restrict__ Wh, const float* __restrict__ We,
    const float* __restrict__ Wv, float* __restrict__ out)
{
    float* hs  = k5_smem;                  // 512*16
    float* zs  = hs + 8192;                // 512*16
    float* E   = zs + 8192;                // 64 * 516
    float* red = E + 64 * K5_EPAD;         // 256
    float* inv = red + 256;                // 64
    float* ws  = inv + 64;                 // Wh[256] | We[256] | Wv[16]

    const int tid = threadIdx.x;
    const int t   = blockIdx.x;

    const float4* hg = (const float4*)(g_h + (size_t)t * BB * 16);
    const float4* zg = (const float4*)(g_z + (size_t)t * BB * 16);
    float4* hs4 = (float4*)hs;
    float4* zs4 = (float4*)zs;
#pragma unroll
    for (int i = 0; i < 8; i++) {
        hs4[i * 256 + tid] = hg[i * 256 + tid];
        zs4[i * 256 + tid] = zg[i * 256 + tid];
    }
    ws[tid]       = Wh[tid];
    ws[256 + tid] = We[tid];
    if (tid < 16) ws[512 + tid] = Wv[tid];
    __syncthreads();

    const int bq0 = tid;
    const int bq1 = tid + 256;
    ull hra[8], hrb[8];
    {
        const ulonglong2* ha = (const ulonglong2*)(hs + bq0 * 16);
        const ulonglong2* hb = (const ulonglong2*)(hs + bq1 * 16);
#pragma unroll
        for (int i = 0; i < 4; i++) {
            ulonglong2 va = ha[i], vb = hb[i];
            hra[2 * i] = va.x; hra[2 * i + 1] = va.y;
            hrb[2 * i] = vb.x; hrb[2 * i + 1] = vb.y;
        }
    }
    ull ctxa[8], ctxb[8];
#pragma unroll
    for (int d = 0; d < 8; d++) { ctxa[d] = 0ull; ctxb[d] = 0ull; }

    for (int tile = 0; tile < 8; tile++) {
        // --- scores + exp for 64 softmax-columns, 2 query rows/thread ---
#pragma unroll 4
        for (int cc = 0; cc < 64; cc++) {
            const ulonglong2* zp = (const ulonglong2*)(zs + (tile * 64 + cc) * 16);
            ulonglong2 z0 = zp[0], z1 = zp[1], z2 = zp[2], z3 = zp[3];
            ull da0 = 0ull, da1 = 0ull, db0 = 0ull, db1 = 0ull;
            da0 = fma2_(hra[0], z0.x, da0); da1 = fma2_(hra[1], z0.y, da1);
            da0 = fma2_(hra[2], z1.x, da0); da1 = fma2_(hra[3], z1.y, da1);
            da0 = fma2_(hra[4], z2.x, da0); da1 = fma2_(hra[5], z2.y, da1);
            da0 = fma2_(hra[6], z3.x, da0); da1 = fma2_(hra[7], z3.y, da1);
            db0 = fma2_(hrb[0], z0.x, db0); db1 = fma2_(hrb[1], z0.y, db1);
            db0 = fma2_(hrb[2], z1.x, db0); db1 = fma2_(hrb[3], z1.y, db1);
            db0 = fma2_(hrb[4], z2.x, db0); db1 = fma2_(hrb[5], z2.y, db1);
            db0 = fma2_(hrb[6], z3.x, db0); db1 = fma2_(hrb[7], z3.y, db1);
            float2 a0 = unpk(da0), a1 = unpk(da1);
            float2 b0 = unpk(db0), b1 = unpk(db1);
            E[cc * K5_EPAD + bq0] = __expf((a0.x + a0.y) + (a1.x + a1.y));
            E[cc * K5_EPAD + bq1] = __expf((b0.x + b0.y) + (b1.x + b1.y));
        }
        __syncthreads();
        // --- column sums (over b): bank = lane, conflict-free ---
        {
            int cc = tid >> 2, seg = tid & 3;
            float s0 = 0.0f, s1 = 0.0f, s2 = 0.0f, s3 = 0.0f;
            const float* ep = E + cc * K5_EPAD + seg;
#pragma unroll 8
            for (int j = 0; j < 32; j++) {
                s0 += ep[16 * j + 0];
                s1 += ep[16 * j + 4];
                s2 += ep[16 * j + 8];
                s3 += ep[16 * j + 12];
            }
            red[tid] = (s0 + s1) + (s2 + s3);
        }
        __syncthreads();
        if (tid < 64) {
            float s = (red[4 * tid] + red[4 * tid + 1])
                    + (red[4 * tid + 2] + red[4 * tid + 3]);
            inv[tid] = 1.0f / s;
        }
        __syncthreads();
        // --- context accumulation ---
#pragma unroll 4
        for (int cc = 0; cc < 64; cc++) {
            float ic = inv[cc];
            float wv0 = E[cc * K5_EPAD + bq0] * ic;
            float wv1 = E[cc * K5_EPAD + bq1] * ic;
            ull w0 = pack2(wv0), w1 = pack2(wv1);
            const ulonglong2* hp2 = (const ulonglong2*)(hs + (tile * 64 + cc) * 16);
            ulonglong2 h0 = hp2[0], h1 = hp2[1], h2 = hp2[2], h3 = hp2[3];
            ctxa[0] = fma2_(w0, h0.x, ctxa[0]); ctxa[1] = fma2_(w0, h0.y, ctxa[1]);
            ctxa[2] = fma2_(w0, h1.x, ctxa[2]); ctxa[3] = fma2_(w0, h1.y, ctxa[3]);
            ctxa[4] = fma2_(w0, h2.x, ctxa[4]); ctxa[5] = fma2_(w0, h2.y, ctxa[5]);
            ctxa[6] = fma2_(w0, h3.x, ctxa[6]); ctxa[7] = fma2_(w0, h3.y, ctxa[7]);
            ctxb[0] = fma2_(w1, h0.x, ctxb[0]); ctxb[1] = fma2_(w1, h0.y, ctxb[1]);
            ctxb[2] = fma2_(w1, h1.x, ctxb[2]); ctxb[3] = fma2_(w1, h1.y, ctxb[3]);
            ctxb[4] = fma2_(w1, h2.x, ctxb[4]); ctxb[5] = fma2_(w1, h2.y, ctxb[5]);
            ctxb[6] = fma2_(w1, h3.x, ctxb[6]); ctxb[7] = fma2_(w1, h3.y, ctxb[7]);
        }
        __syncthreads();
    }

    // --- scoring epilogue for both rows ---
#pragma unroll
    for (int half = 0; half < 2; half++) {
        float hr[16], cx[16];
#pragma unroll
        for (int d = 0; d < 8; d++) {
            float2 a = unpk(half ? hrb[d] : hra[d]);
            float2 b = unpk(half ? ctxb[d] : ctxa[d]);
            hr[2 * d] = a.x; hr[2 * d + 1] = a.y;
            cx[2 * d] = b.x; cx[2 * d + 1] = b.y;
        }
        float p = 0.0f;
#pragma unroll
        for (int d = 0; d < 16; d++) {
            float s = 0.0f;
#pragma unroll
            for (int e = 0; e < 16; e++) s = fmaf(hr[e], ws[d * 16 + e], s);
#pragma unroll
            for (int e = 0; e < 16; e++) s = fmaf(cx[e], ws[256 + d * 16 + e], s);
            p = fmaf(tanhf(s), ws[512 + d], p);
        }
        out[(size_t)t * BB + (half ? bq1 : bq0)] = sigmoidf_fast(p);
    }
}

// ---------------------------------------------------------------------------
extern "C" void kernel_launch(void* const* d_in, const int* in_sizes, int n_in,
                              void* d_out, int out_size)
{
    const float* X     = (const float*)d_in[0];
    const float* Wih_f = (const float*)d_in[1];
    const float* Whh_f = (const float*)d_in[2];
    const float* bih_f = (const float*)d_in[3];
    const float* bhh_f = (const float*)d_in[4];
    const float* Wih_b = (const float*)d_in[5];
    const float* Whh_b = (const float*)d_in[6];
    const float* bih_b = (const float*)d_in[7];
    const float* bhh_b = (const float*)d_in[8];
    const float* Wih_p = (const float*)d_in[9];
    const float* Whh_p = (const float*)d_in[10];
    const float* bih_p = (const float*)d_in[11];
    const float* bhh_p = (const float*)d_in[12];
    const float* W_h   = (const float*)d_in[13];
    const float* W_e   = (const float*)d_in[14];
    const float* W_v   = (const float*)d_in[15];
    float* out = (float*)d_out;

    cudaFuncSetAttribute(k1_proj_mma, cudaFuncAttributeMaxDynamicSharedMemorySize,
                         K1_SMEM_TOTAL);
    cudaFuncSetAttribute(k5_attn, cudaFuncAttributeMaxDynamicSharedMemorySize,
                         K5_SMEM_BYTES);

    k1_proj_mma<<<512, 256, K1_SMEM_TOTAL>>>(X, Wih_f, Wih_b,
                                             bih_f, bhh_f, bih_b, bhh_b);
    k2_bilstm<<<256, 128>>>(Whh_f, Whh_b);
    k4_ptr<<<128, 128>>>(Wih_p, Whh_p, bih_p, bhh_p);
    k5_attn<<<TT, 256, K5_SMEM_BYTES>>>(W_h, W_e, W_v, out);
}

// round 8
// speedup vs baseline: 1.6388x; 1.0762x over previous
#include <cuda_runtime.h>
#include <cuda_fp16.h>

// Problem constants
#define TT 128
#define BB 512
#define DD 768

typedef unsigned long long ull;

// Scratch (device globals — no runtime allocation allowed)
__device__ float g_G[(size_t)TT * BB * 64];     // gates [t][b][64] (bias included)
__device__ float g_h[(size_t)TT * BB * 16];     // bi-LSTM hidden [t][b][16]
__device__ float g_z[(size_t)TT * BB * 16];     // ptr-LSTM hidden [t][b][16]
__device__ float g_part[(size_t)512 * BB * 16]; // k5a partial contexts [block][b][16]

__device__ __forceinline__ float sigmoidf_fast(float x) {
    return 1.0f / (1.0f + __expf(-x));
}

// ---- packed f32x2 helpers ----
__device__ __forceinline__ ull fma2_(ull a, ull b, ull c) {
    ull d;
    asm("fma.rn.f32x2 %0, %1, %2, %3;" : "=l"(d) : "l"(a), "l"(b), "l"(c));
    return d;
}
__device__ __forceinline__ ull pack2(float x) {
    ull d;
    asm("mov.b64 %0, {%1, %1};" : "=l"(d) : "f"(x));
    return d;
}
__device__ __forceinline__ float2 unpk(ull v) {
    float lo, hi;
    asm("mov.b64 {%0, %1}, %2;" : "=f"(lo), "=f"(hi) : "l"(v));
    return make_float2(lo, hi);
}

// ---- warp-level MMA helpers (arch-unconditional: sm_80+ PTX) ----
__device__ __forceinline__ unsigned smem_u32(const void* p) {
    unsigned a;
    asm("{ .reg .u64 t; cvta.to.shared.u64 t, %1; cvt.u32.u64 %0, t; }"
        : "=r"(a) : "l"(p));
    return a;
}
__device__ __forceinline__ void mma16816h(float* d, const unsigned* a, const unsigned* b) {
    asm volatile(
        "mma.sync.aligned.m16n8k16.row.col.f32.f16.f16.f32 "
        "{%0,%1,%2,%3}, {%4,%5,%6,%7}, {%8,%9}, {%0,%1,%2,%3};"
        : "+f"(d[0]), "+f"(d[1]), "+f"(d[2]), "+f"(d[3])
        : "r"(a[0]), "r"(a[1]), "r"(a[2]), "r"(a[3]), "r"(b[0]), "r"(b[1]));
}
__device__ __forceinline__ void ldsm4(unsigned* r, unsigned addr) {
    asm volatile("ldmatrix.sync.aligned.m8n8.x4.shared.b16 {%0,%1,%2,%3}, [%4];"
                 : "=r"(r[0]), "=r"(r[1]), "=r"(r[2]), "=r"(r[3]) : "r"(addr));
}

// ---------------------------------------------------------------------------
// K1 (HMMA, single-product fp16): G = fp16(X) @ fp16(Wcat)^T + bias.
// Dropped residuals (x-x16)*w and x16*(w-w16) are each ~2^-12 relative;
// measured output error of the 2-product variant (one residual dropped) was
// 2.0e-5 -> this variant ~4e-5, tolerance 1e-3.
// 512 blocks x 256 thr, BM=128, N=64, 12 K-chunks of 64. Double-buffered
// smem, one syncthreads per chunk, LDG prefetch hidden under MMA.
// Swizzle: 16B-chunk index ^= row&7 -> conflict-free ldmatrix.
// ---------------------------------------------------------------------------
#define K1_X16  0                       // 2 x 128x64 fp16 = 2 x 16KB
#define K1_WHI  (2 * 16384)             // 2 x 64x64 fp16 = 2 x 8KB
#define K1_BIAS (K1_WHI + 2 * 8192)
#define K1_SMEM_TOTAL (K1_BIAS + 256)

extern __shared__ char k1s[];

__global__ __launch_bounds__(256) void k1_proj_mma(
    const float* __restrict__ X,
    const float* __restrict__ Wf, const float* __restrict__ Wb,
    const float* __restrict__ bf1, const float* __restrict__ bf2,
    const float* __restrict__ bb1, const float* __restrict__ bb2)
{
    const int tid  = threadIdx.x;
    const int wid  = tid >> 5;
    const int lane = tid & 31;
    const int r0   = blockIdx.x * 128;
    const unsigned sb = smem_u32(k1s);

    float* bias = (float*)(k1s + K1_BIAS);
    if (tid < 64)
        bias[tid] = (tid < 32) ? (bf1[tid] + bf2[tid])
                               : (bb1[tid - 32] + bb2[tid - 32]);

    const int arow = tid >> 3;   // 0..31
    const int acg  = tid & 7;    // 16B chunk within 64-col tile

    const int qr = lane & 7;
    const int hm = (lane >> 3) & 1;
    const int hk = lane >> 4;

    const float* xrows[4];
    const float* wrows[2];
#pragma unroll
    for (int sub = 0; sub < 4; sub++)
        xrows[sub] = X + (size_t)(r0 + sub * 32 + arow) * DD + acg * 8;
#pragma unroll
    for (int sub = 0; sub < 2; sub++) {
        int row = sub * 32 + arow;
        wrows[sub] = ((row < 32) ? (Wf + (size_t)row * DD)
                                 : (Wb + (size_t)(row - 32) * DD)) + acg * 8;
    }

    float acc[8][4];
#pragma unroll
    for (int n = 0; n < 8; n++)
#pragma unroll
        for (int i = 0; i < 4; i++) acc[n][i] = 0.0f;

    // prefetch chunk 0
    float4 xp[4][2], wp[2][2];
#pragma unroll
    for (int sub = 0; sub < 4; sub++) {
        xp[sub][0] = *(const float4*)(xrows[sub] + 0);
        xp[sub][1] = *(const float4*)(xrows[sub] + 4);
    }
#pragma unroll
    for (int sub = 0; sub < 2; sub++) {
        wp[sub][0] = *(const float4*)(wrows[sub] + 0);
        wp[sub][1] = *(const float4*)(wrows[sub] + 4);
    }

    for (int c = 0; c < 12; c++) {
        const int p = c & 1;
        char* xbuf = k1s + K1_X16 + p * 16384;
        char* hbuf = k1s + K1_WHI + p * 8192;

        // convert prefetched regs -> fp16 tiles (swizzled)
#pragma unroll
        for (int sub = 0; sub < 4; sub++) {
            float xs[8];
            *(float4*)&xs[0] = xp[sub][0];
            *(float4*)&xs[4] = xp[sub][1];
            unsigned hv[4];
#pragma unroll
            for (int q = 0; q < 4; q++) {
                __half2 h2 = __floats2half2_rn(xs[2 * q], xs[2 * q + 1]);
                hv[q] = *(unsigned*)&h2;
            }
            int row = sub * 32 + arow;
            unsigned off = (unsigned)row * 128 + (unsigned)(acg ^ (row & 7)) * 16;
            *(uint4*)(xbuf + off) = make_uint4(hv[0], hv[1], hv[2], hv[3]);
        }
#pragma unroll
        for (int sub = 0; sub < 2; sub++) {
            float xs[8];
            *(float4*)&xs[0] = wp[sub][0];
            *(float4*)&xs[4] = wp[sub][1];
            unsigned hv[4];
#pragma unroll
            for (int q = 0; q < 4; q++) {
                __half2 h2 = __floats2half2_rn(xs[2 * q], xs[2 * q + 1]);
                hv[q] = *(unsigned*)&h2;
            }
            int row = sub * 32 + arow;
            unsigned off = (unsigned)row * 128 + (unsigned)(acg ^ (row & 7)) * 16;
            *(uint4*)(hbuf + off) = make_uint4(hv[0], hv[1], hv[2], hv[3]);
        }
        __syncthreads();

        // prefetch chunk c+1 (hidden under MMA)
        if (c + 1 < 12) {
            const int kn = (c + 1) * 64;
#pragma unroll
            for (int sub = 0; sub < 4; sub++) {
                xp[sub][0] = *(const float4*)(xrows[sub] + kn);
                xp[sub][1] = *(const float4*)(xrows[sub] + kn + 4);
            }
#pragma unroll
            for (int sub = 0; sub < 2; sub++) {
                wp[sub][0] = *(const float4*)(wrows[sub] + kn);
                wp[sub][1] = *(const float4*)(wrows[sub] + kn + 4);
            }
        }

        // MMA: 4 k-steps of 16
        const unsigned xb = sb + K1_X16 + p * 16384;
        const unsigned hb = sb + K1_WHI + p * 8192;
#pragma unroll
        for (int ks = 0; ks < 4; ks++) {
            int ar = wid * 16 + hm * 8 + qr;
            unsigned ac = (unsigned)((2 * ks + hk) ^ (ar & 7));
            unsigned aoff = (unsigned)ar * 128 + ac * 16;
            unsigned ax[4];
            ldsm4(ax, xb + aoff);
#pragma unroll
            for (int pp = 0; pp < 4; pp++) {
                int g = pp * 16 + hk * 8 + qr;
                unsigned bc = (unsigned)((2 * ks + hm) ^ (g & 7));
                unsigned boff = (unsigned)g * 128 + bc * 16;
                unsigned bhi[4];
                ldsm4(bhi, hb + boff);
                mma16816h(acc[2 * pp],     ax, bhi);
                mma16816h(acc[2 * pp + 1], ax, bhi + 2);
            }
        }
    }

    // epilogue
    const int mrow = r0 + wid * 16 + (lane >> 2);
    const int cb   = (lane & 3) * 2;
#pragma unroll
    for (int nt = 0; nt < 8; nt++) {
        int col = nt * 8 + cb;
        float b0 = bias[col], b1 = bias[col + 1];
        *(float2*)(g_G + (size_t)mrow * 64 + col) =
            make_float2(acc[nt][0] + b0, acc[nt][1] + b1);
        *(float2*)(g_G + (size_t)(mrow + 8) * 64 + col) =
            make_float2(acc[nt][2] + b0, acc[nt][3] + b1);
    }
}

// ---------------------------------------------------------------------------
// K2: bi-LSTM scans (fwd + bwd), one warp per (batch item, direction).
// ---------------------------------------------------------------------------
__global__ __launch_bounds__(128) void k2_bilstm(
    const float* __restrict__ Whhf, const float* __restrict__ Whhb)
{
    const unsigned FULL = 0xffffffffu;
    int warp = blockIdx.x * (blockDim.x >> 5) + (threadIdx.x >> 5); // 0..1023
    int lane = threadIdx.x & 31;
    int dir  = warp >> 9;
    int b    = warp & 511;

    const float* Whh = dir ? Whhb : Whhf;
    float w[8];
#pragma unroll
    for (int k = 0; k < 8; k++) w[k] = Whh[lane * 8 + k];

    float hrep[8];
#pragma unroll
    for (int k = 0; k < 8; k++) hrep[k] = 0.0f;
    float c = 0.0f;

    const int coloff = dir * 32 + lane;
    int t0 = dir ? (TT - 1) : 0;
    float gcur = g_G[((size_t)t0 * BB + b) * 64 + coloff];

    for (int s = 0; s < TT; s++) {
        int t = dir ? (TT - 1 - s) : s;
        float gnext = 0.0f;
        if (s + 1 < TT) {
            int tn = dir ? (TT - 2 - s) : (s + 1);
            gnext = g_G[((size_t)tn * BB + b) * 64 + coloff];
        }
        float gate = gcur;
#pragma unroll
        for (int k = 0; k < 8; k++) gate = fmaf(hrep[k], w[k], gate);

        float a = (lane >= 16 && lane < 24) ? tanhf(gate) : sigmoidf_fast(gate);
        float fv = __shfl_sync(FULL, a, lane + 8);
        float gv = __shfl_sync(FULL, a, lane + 16);
        float ov = __shfl_sync(FULL, a, lane + 24);

        float hnew = 0.0f;
        if (lane < 8) {
            c = fmaf(fv, c, a * gv);
            hnew = ov * tanhf(c);
            g_h[((size_t)t * BB + b) * 16 + dir * 8 + lane] = hnew;
        }
#pragma unroll
        for (int k = 0; k < 8; k++) hrep[k] = __shfl_sync(FULL, hnew, k);
        gcur = gnext;
    }
}

// ---------------------------------------------------------------------------
// K4: ptr-LSTM scan, one warp per batch item.
// ---------------------------------------------------------------------------
__global__ __launch_bounds__(128) void k4_ptr(
    const float* __restrict__ Wih, const float* __restrict__ Whh,
    const float* __restrict__ b1, const float* __restrict__ b2)
{
    const unsigned FULL = 0xffffffffu;
    int warp = blockIdx.x * (blockDim.x >> 5) + (threadIdx.x >> 5); // 0..511
    int lane = threadIdx.x & 31;
    int b    = warp;

    const int r0 = lane, r1 = lane + 32;
    float wi0[16], wi1[16], wh0[16], wh1[16];
#pragma unroll
    for (int k = 0; k < 16; k++) {
        wi0[k] = Wih[r0 * 16 + k];
        wi1[k] = Wih[r1 * 16 + k];
        wh0[k] = Whh[r0 * 16 + k];
        wh1[k] = Whh[r1 * 16 + k];
    }
    const float bias0 = b1[r0] + b2[r0];
    const float bias1 = b1[r1] + b2[r1];

    float zrep[16];
#pragma unroll
    for (int k = 0; k < 16; k++) zrep[k] = 0.0f;
    float c = 0.0f;

    const float4* hp = (const float4*)g_h;
    size_t base = ((size_t)0 * BB + b) * 4;
    float4 x0 = hp[base + 0], x1 = hp[base + 1], x2 = hp[base + 2], x3 = hp[base + 3];

    for (int t = 0; t < TT; t++) {
        float4 n0 = x0, n1 = x1, n2 = x2, n3 = x3;
        if (t + 1 < TT) {
            size_t nb = ((size_t)(t + 1) * BB + b) * 4;
            n0 = hp[nb + 0]; n1 = hp[nb + 1]; n2 = hp[nb + 2]; n3 = hp[nb + 3];
        }
        float xin[16] = {x0.x, x0.y, x0.z, x0.w, x1.x, x1.y, x1.z, x1.w,
                         x2.x, x2.y, x2.z, x2.w, x3.x, x3.y, x3.z, x3.w};
        float u0 = bias0, u1 = bias1;
#pragma unroll
        for (int k = 0; k < 16; k++) {
            u0 = fmaf(xin[k], wi0[k], u0);
            u1 = fmaf(xin[k], wi1[k], u1);
        }
#pragma unroll
        for (int k = 0; k < 16; k++) {
            u0 = fmaf(zrep[k], wh0[k], u0);
            u1 = fmaf(zrep[k], wh1[k], u1);
        }
        float a0 = sigmoidf_fast(u0);
        float a1 = (lane < 16) ? tanhf(u1) : sigmoidf_fast(u1);
        float fv = __shfl_sync(FULL, a0, lane + 16);
        float ov = __shfl_sync(FULL, a1, lane + 16);

        float zn = 0.0f;
        if (lane < 16) {
            c = fmaf(fv, c, a0 * a1);
            zn = ov * tanhf(c);
            g_z[((size_t)t * BB + b) * 16 + lane] = zn;
        }
#pragma unroll
        for (int k = 0; k < 16; k++) zrep[k] = __shfl_sync(FULL, zn, k);
        x0 = n0; x1 = n1; x2 = n2; x3 = n3;
    }
}

// ---------------------------------------------------------------------------
// K5a: attention partials. Grid 512 = (t, quarter q). Each block owns 128
// softmax-columns (columns are self-contained under dim-1 softmax: the
// block computes its own colsums). 4 tiles of 32 columns; E pad 520 makes
// colsum banks 8c+seg conflict-free. Partial ctx -> g_part (fixed-order
// combine in k5b: deterministic). 2 blocks/SM (smem ~106KB).
// ---------------------------------------------------------------------------
#define K5A_EPAD 520
#define K5A_SMEM_FLOATS (8192 + 2048 + 32 * K5A_EPAD + 256 + 32)
#define K5A_SMEM_BYTES  (K5A_SMEM_FLOATS * 4)

extern __shared__ float k5a_smem[];

__global__ __launch_bounds__(256, 2) void k5a_attn()
{
    float* hs  = k5a_smem;                 // 512*16
    float* zs  = hs + 8192;                // 128*16 (this block's columns)
    float* E   = zs + 2048;                // 32 * 520
    float* red = E + 32 * K5A_EPAD;        // 256
    float* inv = red + 256;                // 32

    const int tid = threadIdx.x;
    const int t   = blockIdx.x >> 2;
    const int q   = blockIdx.x & 3;

    const float4* hg = (const float4*)(g_h + (size_t)t * BB * 16);
    const float4* zg = (const float4*)(g_z + ((size_t)t * BB + q * 128) * 16);
    float4* hs4 = (float4*)hs;
    float4* zs4 = (float4*)zs;
#pragma unroll
    for (int i = 0; i < 8; i++) hs4[i * 256 + tid] = hg[i * 256 + tid];
#pragma unroll
    for (int i = 0; i < 2; i++) zs4[i * 256 + tid] = zg[i * 256 + tid];
    __syncthreads();

    const int bq0 = tid;
    const int bq1 = tid + 256;
    ull hra[8], hrb[8];
    {
        const ulonglong2* ha = (const ulonglong2*)(hs + bq0 * 16);
        const ulonglong2* hb = (const ulonglong2*)(hs + bq1 * 16);
#pragma unroll
        for (int i = 0; i < 4; i++) {
            ulonglong2 va = ha[i], vb = hb[i];
            hra[2 * i] = va.x; hra[2 * i + 1] = va.y;
            hrb[2 * i] = vb.x; hrb[2 * i + 1] = vb.y;
        }
    }
    ull ctxa[8], ctxb[8];
#pragma unroll
    for (int d = 0; d < 8; d++) { ctxa[d] = 0ull; ctxb[d] = 0ull; }

    for (int tile = 0; tile < 4; tile++) {
        // --- scores + exp for 32 columns, 2 query rows/thread ---
#pragma unroll 4
        for (int cc = 0; cc < 32; cc++) {
            const ulonglong2* zp = (const ulonglong2*)(zs + (tile * 32 + cc) * 16);
            ulonglong2 z0 = zp[0], z1 = zp[1], z2 = zp[2], z3 = zp[3];
            ull da0 = 0ull, da1 = 0ull, db0 = 0ull, db1 = 0ull;
            da0 = fma2_(hra[0], z0.x, da0); da1 = fma2_(hra[1], z0.y, da1);
            da0 = fma2_(hra[2], z1.x, da0); da1 = fma2_(hra[3], z1.y, da1);
            da0 = fma2_(hra[4], z2.x, da0); da1 = fma2_(hra[5], z2.y, da1);
            da0 = fma2_(hra[6], z3.x, da0); da1 = fma2_(hra[7], z3.y, da1);
            db0 = fma2_(hrb[0], z0.x, db0); db1 = fma2_(hrb[1], z0.y, db1);
            db0 = fma2_(hrb[2], z1.x, db0); db1 = fma2_(hrb[3], z1.y, db1);
            db0 = fma2_(hrb[4], z2.x, db0); db1 = fma2_(hrb[5], z2.y, db1);
            db0 = fma2_(hrb[6], z3.x, db0); db1 = fma2_(hrb[7], z3.y, db1);
            float2 a0 = unpk(da0), a1 = unpk(da1);
            float2 b0 = unpk(db0), b1 = unpk(db1);
            E[cc * K5A_EPAD + bq0] = __expf((a0.x + a0.y) + (a1.x + a1.y));
            E[cc * K5A_EPAD + bq1] = __expf((b0.x + b0.y) + (b1.x + b1.y));
        }
        __syncthreads();
        // --- column sums (32 cols x 8 segs): banks 8c+seg, conflict-free ---
        {
            int cc = tid >> 3, seg = tid & 7;
            float s0 = 0.0f, s1 = 0.0f;
            const float* ep = E + cc * K5A_EPAD + seg;
#pragma unroll 8
            for (int j = 0; j < 32; j++) {
                s0 += ep[16 * j + 0];
                s1 += ep[16 * j + 8];
            }
            red[tid] = s0 + s1;
        }
        __syncthreads();
        if (tid < 32) {
            float s = 0.0f;
#pragma unroll
            for (int r = 0; r < 8; r++) s += red[tid * 8 + r];
            inv[tid] = 1.0f / s;
        }
        __syncthreads();
        // --- partial context accumulation ---
#pragma unroll 4
        for (int cc = 0; cc < 32; cc++) {
            float ic = inv[cc];
            float wv0 = E[cc * K5A_EPAD + bq0] * ic;
            float wv1 = E[cc * K5A_EPAD + bq1] * ic;
            ull w0 = pack2(wv0), w1 = pack2(wv1);
            const ulonglong2* hp2 =
                (const ulonglong2*)(hs + (q * 128 + tile * 32 + cc) * 16);
            ulonglong2 h0 = hp2[0], h1 = hp2[1], h2 = hp2[2], h3 = hp2[3];
            ctxa[0] = fma2_(w0, h0.x, ctxa[0]); ctxa[1] = fma2_(w0, h0.y, ctxa[1]);
            ctxa[2] = fma2_(w0, h1.x, ctxa[2]); ctxa[3] = fma2_(w0, h1.y, ctxa[3]);
            ctxa[4] = fma2_(w0, h2.x, ctxa[4]); ctxa[5] = fma2_(w0, h2.y, ctxa[5]);
            ctxa[6] = fma2_(w0, h3.x, ctxa[6]); ctxa[7] = fma2_(w0, h3.y, ctxa[7]);
            ctxb[0] = fma2_(w1, h0.x, ctxb[0]); ctxb[1] = fma2_(w1, h0.y, ctxb[1]);
            ctxb[2] = fma2_(w1, h1.x, ctxb[2]); ctxb[3] = fma2_(w1, h1.y, ctxb[3]);
            ctxb[4] = fma2_(w1, h2.x, ctxb[4]); ctxb[5] = fma2_(w1, h2.y, ctxb[5]);
            ctxb[6] = fma2_(w1, h3.x, ctxb[6]); ctxb[7] = fma2_(w1, h3.y, ctxb[7]);
        }
        __syncthreads();
    }

    // --- write partial contexts ---
    float* pa = g_part + ((size_t)blockIdx.x * BB + bq0) * 16;
    float* pb = g_part + ((size_t)blockIdx.x * BB + bq1) * 16;
#pragma unroll
    for (int i = 0; i < 4; i++) {
        float2 a0 = unpk(ctxa[2 * i]), a1 = unpk(ctxa[2 * i + 1]);
        *(float4*)(pa + 4 * i) = make_float4(a0.x, a0.y, a1.x, a1.y);
        float2 b0 = unpk(ctxb[2 * i]), b1 = unpk(ctxb[2 * i + 1]);
        *(float4*)(pb + 4 * i) = make_float4(b0.x, b0.y, b1.x, b1.y);
    }
}

// ---------------------------------------------------------------------------
// K5b: combine partials (fixed order -> deterministic) + scoring epilogue.
// Grid 128 (t), 512 threads (b).
// ---------------------------------------------------------------------------
__global__ __launch_bounds__(512) void k5b_score(
    const float* __restrict__ Wh, const float* __restrict__ We,
    const float* __restrict__ Wv, float* __restrict__ out)
{
    __shared__ float ws[528];   // Wh[256] | We[256] | Wv[16]
    const int tid = threadIdx.x;
    const int t   = blockIdx.x;

    if (tid < 256)      ws[tid] = Wh[tid];
    else if (tid < 512) ws[tid] = We[tid - 256];
    if (tid < 16)       ws[512 + tid] = Wv[tid];
    __syncthreads();

    float hr[16], cx[16];
    {
        const float4* hp = (const float4*)(g_h + ((size_t)t * BB + tid) * 16);
#pragma unroll
        for (int i = 0; i < 4; i++) *(float4*)&hr[4 * i] = hp[i];
    }
#pragma unroll
    for (int d = 0; d < 16; d++) cx[d] = 0.0f;
#pragma unroll
    for (int q = 0; q < 4; q++) {
        const float4* pp =
            (const float4*)(g_part + ((size_t)(t * 4 + q) * BB + tid) * 16);
#pragma unroll
        for (int i = 0; i < 4; i++) {
            float4 v = pp[i];
            cx[4 * i + 0] += v.x; cx[4 * i + 1] += v.y;
            cx[4 * i + 2] += v.z; cx[4 * i + 3] += v.w;
        }
    }

    float p = 0.0f;
#pragma unroll
    for (int d = 0; d < 16; d++) {
        float s = 0.0f;
#pragma unroll
        for (int e = 0; e < 16; e++) s = fmaf(hr[e], ws[d * 16 + e], s);
#pragma unroll
        for (int e = 0; e < 16; e++) s = fmaf(cx[e], ws[256 + d * 16 + e], s);
        p = fmaf(tanhf(s), ws[512 + d], p);
    }
    out[(size_t)t * BB + tid] = sigmoidf_fast(p);
}

// ---------------------------------------------------------------------------
extern "C" void kernel_launch(void* const* d_in, const int* in_sizes, int n_in,
                              void* d_out, int out_size)
{
    const float* X     = (const float*)d_in[0];
    const float* Wih_f = (const float*)d_in[1];
    const float* Whh_f = (const float*)d_in[2];
    const float* bih_f = (const float*)d_in[3];
    const float* bhh_f = (const float*)d_in[4];
    const float* Wih_b = (const float*)d_in[5];
    const float* Whh_b = (const float*)d_in[6];
    const float* bih_b = (const float*)d_in[7];
    const float* bhh_b = (const float*)d_in[8];
    const float* Wih_p = (const float*)d_in[9];
    const float* Whh_p = (const float*)d_in[10];
    const float* bih_p = (const float*)d_in[11];
    const float* bhh_p = (const float*)d_in[12];
    const float* W_h   = (const float*)d_in[13];
    const float* W_e   = (const float*)d_in[14];
    const float* W_v   = (const float*)d_in[15];
    float* out = (float*)d_out;

    cudaFuncSetAttribute(k1_proj_mma, cudaFuncAttributeMaxDynamicSharedMemorySize,
                         K1_SMEM_TOTAL);
    cudaFuncSetAttribute(k5a_attn, cudaFuncAttributeMaxDynamicSharedMemorySize,
                         K5A_SMEM_BYTES);

    k1_proj_mma<<<512, 256, K1_SMEM_TOTAL>>>(X, Wih_f, Wih_b,
                                             bih_f, bhh_f, bih_b, bhh_b);
    k2_bilstm<<<256, 128>>>(Whh_f, Whh_b);
    k4_ptr<<<128, 128>>>(Wih_p, Whh_p, bih_p, bhh_p);
    k5a_attn<<<512, 256, K5A_SMEM_BYTES>>>();
    k5b_score<<<128, 512>>>(W_h, W_e, W_v, out);
}

// round 9
// speedup vs baseline: 1.8517x; 1.1299x over previous
#include <cuda_runtime.h>
#include <cuda_fp16.h>

// Problem constants
#define TT 128
#define BB 512
#define DD 768

typedef unsigned long long ull;

// Scratch (device globals — no runtime allocation allowed)
__device__ float  g_G[(size_t)TT * BB * 64];     // gates [t][b][64] (bias included)
__device__ float  g_h[(size_t)TT * BB * 16];     // bi-LSTM hidden [t][b][16]
__device__ float  g_z[(size_t)TT * BB * 16];     // ptr-LSTM hidden [t][b][16]
__device__ float  g_part[(size_t)512 * BB * 16]; // k5a partial contexts
__device__ __half g_W16[64 * DD];                // fp16 Wcat (rows 0-31 f, 32-63 b)

__device__ __forceinline__ float tanh_ap(float x) {
    float y;
    asm("tanh.approx.f32 %0, %1;" : "=f"(y) : "f"(x));
    return y;
}
__device__ __forceinline__ float sig_ap(float x) {
    return fmaf(0.5f, tanh_ap(0.5f * x), 0.5f);
}

// ---- packed f32x2 helpers ----
__device__ __forceinline__ ull fma2_(ull a, ull b, ull c) {
    ull d;
    asm("fma.rn.f32x2 %0, %1, %2, %3;" : "=l"(d) : "l"(a), "l"(b), "l"(c));
    return d;
}
__device__ __forceinline__ ull pack2(float x) {
    ull d;
    asm("mov.b64 %0, {%1, %1};" : "=l"(d) : "f"(x));
    return d;
}
__device__ __forceinline__ float2 unpk(ull v) {
    float lo, hi;
    asm("mov.b64 {%0, %1}, %2;" : "=f"(lo), "=f"(hi) : "l"(v));
    return make_float2(lo, hi);
}

// ---- warp-level MMA helpers (arch-unconditional: sm_80+ PTX) ----
__device__ __forceinline__ unsigned smem_u32(const void* p) {
    unsigned a;
    asm("{ .reg .u64 t; cvta.to.shared.u64 t, %1; cvt.u32.u64 %0, t; }"
        : "=r"(a) : "l"(p));
    return a;
}
__device__ __forceinline__ void mma16816h(float* d, const unsigned* a, const unsigned* b) {
    asm volatile(
        "mma.sync.aligned.m16n8k16.row.col.f32.f16.f16.f32 "
        "{%0,%1,%2,%3}, {%4,%5,%6,%7}, {%8,%9}, {%0,%1,%2,%3};"
        : "+f"(d[0]), "+f"(d[1]), "+f"(d[2]), "+f"(d[3])
        : "r"(a[0]), "r"(a[1]), "r"(a[2]), "r"(a[3]), "r"(b[0]), "r"(b[1]));
}
__device__ __forceinline__ void ldsm4(unsigned* r, unsigned addr) {
    asm volatile("ldmatrix.sync.aligned.m8n8.x4.shared.b16 {%0,%1,%2,%3}, [%4];"
                 : "=r"(r[0]), "=r"(r[1]), "=r"(r[2]), "=r"(r[3]) : "r"(addr));
}

// ---------------------------------------------------------------------------
// K0: one-shot fp16 conversion of Wcat (64 x 768). 24 blocks x 256 thr,
// 8 floats per thread.
// ---------------------------------------------------------------------------
__global__ __launch_bounds__(256) void k0_wcvt(
    const float* __restrict__ Wf, const float* __restrict__ Wb)
{
    int idx = blockIdx.x * 256 + threadIdx.x;      // 0..6143
    int j  = idx / 96;
    int kc = (idx % 96) * 8;
    const float* src = (j < 32) ? (Wf + (size_t)j * DD + kc)
                                : (Wb + (size_t)(j - 32) * DD + kc);
    float4 a = *(const float4*)src;
    float4 b = *(const float4*)(src + 4);
    __half2 h0 = __floats2half2_rn(a.x, a.y);
    __half2 h1 = __floats2half2_rn(a.z, a.w);
    __half2 h2 = __floats2half2_rn(b.x, b.y);
    __half2 h3 = __floats2half2_rn(b.z, b.w);
    uint4 o = make_uint4(*(unsigned*)&h0, *(unsigned*)&h1,
                         *(unsigned*)&h2, *(unsigned*)&h3);
    ((uint4*)g_W16)[idx] = o;
}

// ---------------------------------------------------------------------------
// K1 (HMMA, single-product fp16): G = fp16(X) @ fp16(Wcat)^T + bias.
// W comes pre-converted from g_W16 (no in-kernel W conversion).
// 512 blocks x 256 thr, BM=128, N=64, 12 K-chunks of 64. Double-buffered
// smem, one syncthreads per chunk, LDG prefetch hidden under MMA.
// Swizzle: 16B-chunk index ^= row&7 -> conflict-free ldmatrix.
// ---------------------------------------------------------------------------
#define K1_X16  0                       // 2 x 128x64 fp16 = 2 x 16KB
#define K1_WHI  (2 * 16384)             // 2 x 64x64 fp16 = 2 x 8KB
#define K1_BIAS (K1_WHI + 2 * 8192)
#define K1_SMEM_TOTAL (K1_BIAS + 256)

extern __shared__ char k1s[];

__global__ __launch_bounds__(256) void k1_proj_mma(
    const float* __restrict__ X,
    const float* __restrict__ bf1, const float* __restrict__ bf2,
    const float* __restrict__ bb1, const float* __restrict__ bb2)
{
    const int tid  = threadIdx.x;
    const int wid  = tid >> 5;
    const int lane = tid & 31;
    const int r0   = blockIdx.x * 128;
    const unsigned sb = smem_u32(k1s);

    float* bias = (float*)(k1s + K1_BIAS);
    if (tid < 64)
        bias[tid] = (tid < 32) ? (bf1[tid] + bf2[tid])
                               : (bb1[tid - 32] + bb2[tid - 32]);

    const int arow = tid >> 3;   // 0..31
    const int acg  = tid & 7;    // 16B chunk within 64-col tile

    const int qr = lane & 7;
    const int hm = (lane >> 3) & 1;
    const int hk = lane >> 4;

    const float*  xrows[4];
    const __half* wrows[2];
#pragma unroll
    for (int sub = 0; sub < 4; sub++)
        xrows[sub] = X + (size_t)(r0 + sub * 32 + arow) * DD + acg * 8;
#pragma unroll
    for (int sub = 0; sub < 2; sub++)
        wrows[sub] = g_W16 + (size_t)(sub * 32 + arow) * DD + acg * 8;

    float acc[8][4];
#pragma unroll
    for (int n = 0; n < 8; n++)
#pragma unroll
        for (int i = 0; i < 4; i++) acc[n][i] = 0.0f;

    // prefetch chunk 0
    float4 xp[4][2];
    uint4  wp[2];
#pragma unroll
    for (int sub = 0; sub < 4; sub++) {
        xp[sub][0] = *(const float4*)(xrows[sub] + 0);
        xp[sub][1] = *(const float4*)(xrows[sub] + 4);
    }
#pragma unroll
    for (int sub = 0; sub < 2; sub++)
        wp[sub] = *(const uint4*)(wrows[sub]);

    for (int c = 0; c < 12; c++) {
        const int p = c & 1;
        char* xbuf = k1s + K1_X16 + p * 16384;
        char* hbuf = k1s + K1_WHI + p * 8192;

        // convert prefetched X regs -> fp16 tiles; W goes straight in
#pragma unroll
        for (int sub = 0; sub < 4; sub++) {
            float xs[8];
            *(float4*)&xs[0] = xp[sub][0];
            *(float4*)&xs[4] = xp[sub][1];
            unsigned hv[4];
#pragma unroll
            for (int q = 0; q < 4; q++) {
                __half2 h2 = __floats2half2_rn(xs[2 * q], xs[2 * q + 1]);
                hv[q] = *(unsigned*)&h2;
            }
            int row = sub * 32 + arow;
            unsigned off = (unsigned)row * 128 + (unsigned)(acg ^ (row & 7)) * 16;
            *(uint4*)(xbuf + off) = make_uint4(hv[0], hv[1], hv[2], hv[3]);
        }
#pragma unroll
        for (int sub = 0; sub < 2; sub++) {
            int row = sub * 32 + arow;
            unsigned off = (unsigned)row * 128 + (unsigned)(acg ^ (row & 7)) * 16;
            *(uint4*)(hbuf + off) = wp[sub];
        }
        __syncthreads();

        // prefetch chunk c+1 (hidden under MMA)
        if (c + 1 < 12) {
            const int kn = (c + 1) * 64;
#pragma unroll
            for (int sub = 0; sub < 4; sub++) {
                xp[sub][0] = *(const float4*)(xrows[sub] + kn);
                xp[sub][1] = *(const float4*)(xrows[sub] + kn + 4);
            }
#pragma unroll
            for (int sub = 0; sub < 2; sub++)
                wp[sub] = *(const uint4*)(wrows[sub] + kn);
        }

        // MMA: 4 k-steps of 16
        const unsigned xb = sb + K1_X16 + p * 16384;
        const unsigned hb = sb + K1_WHI + p * 8192;
#pragma unroll
        for (int ks = 0; ks < 4; ks++) {
            int ar = wid * 16 + hm * 8 + qr;
            unsigned ac = (unsigned)((2 * ks + hk) ^ (ar & 7));
            unsigned aoff = (unsigned)ar * 128 + ac * 16;
            unsigned ax[4];
            ldsm4(ax, xb + aoff);
#pragma unroll
            for (int pp = 0; pp < 4; pp++) {
                int g = pp * 16 + hk * 8 + qr;
                unsigned bc = (unsigned)((2 * ks + hm) ^ (g & 7));
                unsigned boff = (unsigned)g * 128 + bc * 16;
                unsigned bhi[4];
                ldsm4(bhi, hb + boff);
                mma16816h(acc[2 * pp],     ax, bhi);
                mma16816h(acc[2 * pp + 1], ax, bhi + 2);
            }
        }
    }

    // epilogue
    const int mrow = r0 + wid * 16 + (lane >> 2);
    const int cb   = (lane & 3) * 2;
#pragma unroll
    for (int nt = 0; nt < 8; nt++) {
        int col = nt * 8 + cb;
        float b0 = bias[col], b1 = bias[col + 1];
        *(float2*)(g_G + (size_t)mrow * 64 + col) =
            make_float2(acc[nt][0] + b0, acc[nt][1] + b1);
        *(float2*)(g_G + (size_t)(mrow + 8) * 64 + col) =
            make_float2(acc[nt][2] + b0, acc[nt][3] + b1);
    }
}

// ---------------------------------------------------------------------------
// K2: bi-LSTM scans (fwd + bwd), one warp per (batch item, direction).
// Approx activations (tanh.approx MUFU) shorten the per-step chain.
// ---------------------------------------------------------------------------
__global__ __launch_bounds__(128) void k2_bilstm(
    const float* __restrict__ Whhf, const float* __restrict__ Whhb)
{
    const unsigned FULL = 0xffffffffu;
    int warp = blockIdx.x * (blockDim.x >> 5) + (threadIdx.x >> 5); // 0..1023
    int lane = threadIdx.x & 31;
    int dir  = warp >> 9;
    int b    = warp & 511;

    const float* Whh = dir ? Whhb : Whhf;
    float w[8];
#pragma unroll
    for (int k = 0; k < 8; k++) w[k] = Whh[lane * 8 + k];

    float hrep[8];
#pragma unroll
    for (int k = 0; k < 8; k++) hrep[k] = 0.0f;
    float c = 0.0f;

    const int coloff = dir * 32 + lane;
    int t0 = dir ? (TT - 1) : 0;
    float gcur = g_G[((size_t)t0 * BB + b) * 64 + coloff];

    for (int s = 0; s < TT; s++) {
        int t = dir ? (TT - 1 - s) : s;
        float gnext = 0.0f;
        if (s + 1 < TT) {
            int tn = dir ? (TT - 2 - s) : (s + 1);
            gnext = g_G[((size_t)tn * BB + b) * 64 + coloff];
        }
        // split dot: two 4-deep chains
        float p0 = gcur, p1 = 0.0f;
#pragma unroll
        for (int k = 0; k < 4; k++) {
            p0 = fmaf(hrep[k], w[k], p0);
            p1 = fmaf(hrep[k + 4], w[k + 4], p1);
        }
        float gate = p0 + p1;

        float a = (lane >= 16 && lane < 24) ? tanh_ap(gate) : sig_ap(gate);
        float fv = __shfl_sync(FULL, a, lane + 8);
        float gv = __shfl_sync(FULL, a, lane + 16);
        float ov = __shfl_sync(FULL, a, lane + 24);

        float hnew = 0.0f;
        if (lane < 8) {
            c = fmaf(fv, c, a * gv);
            hnew = ov * tanh_ap(c);
            g_h[((size_t)t * BB + b) * 16 + dir * 8 + lane] = hnew;
        }
#pragma unroll
        for (int k = 0; k < 8; k++) hrep[k] = __shfl_sync(FULL, hnew, k);
        gcur = gnext;
    }
}

// ---------------------------------------------------------------------------
// K4: ptr-LSTM scan, one warp per batch item. Approx activations; dot
// chains split for shorter dependency depth.
// ---------------------------------------------------------------------------
__global__ __launch_bounds__(128) void k4_ptr(
    const float* __restrict__ Wih, const float* __restrict__ Whh,
    const float* __restrict__ b1, const float* __restrict__ b2)
{
    const unsigned FULL = 0xffffffffu;
    int warp = blockIdx.x * (blockDim.x >> 5) + (threadIdx.x >> 5); // 0..511
    int lane = threadIdx.x & 31;
    int b    = warp;

    const int r0 = lane, r1 = lane + 32;
    float wi0[16], wi1[16], wh0[16], wh1[16];
#pragma unroll
    for (int k = 0; k < 16; k++) {
        wi0[k] = Wih[r0 * 16 + k];
        wi1[k] = Wih[r1 * 16 + k];
        wh0[k] = Whh[r0 * 16 + k];
        wh1[k] = Whh[r1 * 16 + k];
    }
    const float bias0 = b1[r0] + b2[r0];
    const float bias1 = b1[r1] + b2[r1];

    float zrep[16];
#pragma unroll
    for (int k = 0; k < 16; k++) zrep[k] = 0.0f;
    float c = 0.0f;

    const float4* hp = (const float4*)g_h;
    size_t base = ((size_t)0 * BB + b) * 4;
    float4 x0 = hp[base + 0], x1 = hp[base + 1], x2 = hp[base + 2], x3 = hp[base + 3];

    for (int t = 0; t < TT; t++) {
        float4 n0 = x0, n1 = x1, n2 = x2, n3 = x3;
        if (t + 1 < TT) {
            size_t nb = ((size_t)(t + 1) * BB + b) * 4;
            n0 = hp[nb + 0]; n1 = hp[nb + 1]; n2 = hp[nb + 2]; n3 = hp[nb + 3];
        }
        float xin[16] = {x0.x, x0.y, x0.z, x0.w, x1.x, x1.y, x1.z, x1.w,
                         x2.x, x2.y, x2.z, x2.w, x3.x, x3.y, x3.z, x3.w};
        // 4 chains of 8 per gate
        float a0 = bias0, a1 = 0.0f, b0_ = bias1, b1_ = 0.0f;
#pragma unroll
        for (int k = 0; k < 8; k++) {
            a0  = fmaf(xin[k],     wi0[k],     a0);
            a1  = fmaf(xin[k + 8], wi0[k + 8], a1);
            b0_ = fmaf(xin[k],     wi1[k],     b0_);
            b1_ = fmaf(xin[k + 8], wi1[k + 8], b1_);
        }
        float c0 = 0.0f, c1 = 0.0f, d0 = 0.0f, d1 = 0.0f;
#pragma unroll
        for (int k = 0; k < 8; k++) {
            c0 = fmaf(zrep[k],     wh0[k],     c0);
            c1 = fmaf(zrep[k + 8], wh0[k + 8], c1);
            d0 = fmaf(zrep[k],     wh1[k],     d0);
            d1 = fmaf(zrep[k + 8], wh1[k + 8], d1);
        }
        float u0 = (a0 + a1) + (c0 + c1);
        float u1 = (b0_ + b1_) + (d0 + d1);

        float g0 = sig_ap(u0);                             // i (l<16) or f (l>=16)
        float g1 = (lane < 16) ? tanh_ap(u1) : sig_ap(u1); // g or o
        float fv = __shfl_sync(FULL, g0, lane + 16);
        float ov = __shfl_sync(FULL, g1, lane + 16);

        float zn = 0.0f;
        if (lane < 16) {
            c = fmaf(fv, c, g0 * g1);
            zn = ov * tanh_ap(c);
            g_z[((size_t)t * BB + b) * 16 + lane] = zn;
        }
#pragma unroll
        for (int k = 0; k < 16; k++) zrep[k] = __shfl_sync(FULL, zn, k);
        x0 = n0; x1 = n1; x2 = n2; x3 = n3;
    }
}

// ---------------------------------------------------------------------------
// K5a: attention partials. Grid 512 = (t, quarter q). Each block owns 128
// softmax-columns (self-contained colsums). 4 tiles of 32 columns; E pad
// 520 -> conflict-free colsum. Partial ctx -> g_part. 2 blocks/SM.
// ---------------------------------------------------------------------------
#define K5A_EPAD 520
#define K5A_SMEM_FLOATS (8192 + 2048 + 32 * K5A_EPAD + 256 + 32)
#define K5A_SMEM_BYTES  (K5A_SMEM_FLOATS * 4)

extern __shared__ float k5a_smem[];

__global__ __launch_bounds__(256, 2) void k5a_attn()
{
    float* hs  = k5a_smem;                 // 512*16
    float* zs  = hs + 8192;                // 128*16 (this block's columns)
    float* E   = zs + 2048;                // 32 * 520
    float* red = E + 32 * K5A_EPAD;        // 256
    float* inv = red + 256;                // 32

    const int tid = threadIdx.x;
    const int t   = blockIdx.x >> 2;
    const int q   = blockIdx.x & 3;

    const float4* hg = (const float4*)(g_h + (size_t)t * BB * 16);
    const float4* zg = (const float4*)(g_z + ((size_t)t * BB + q * 128) * 16);
    float4* hs4 = (float4*)hs;
    float4* zs4 = (float4*)zs;
#pragma unroll
    for (int i = 0; i < 8; i++) hs4[i * 256 + tid] = hg[i * 256 + tid];
#pragma unroll
    for (int i = 0; i < 2; i++) zs4[i * 256 + tid] = zg[i * 256 + tid];
    __syncthreads();

    const int bq0 = tid;
    const int bq1 = tid + 256;
    ull hra[8], hrb[8];
    {
        const ulonglong2* ha = (const ulonglong2*)(hs + bq0 * 16);
        const ulonglong2* hb = (const ulonglong2*)(hs + bq1 * 16);
#pragma unroll
        for (int i = 0; i < 4; i++) {
            ulonglong2 va = ha[i], vb = hb[i];
            hra[2 * i] = va.x; hra[2 * i + 1] = va.y;
            hrb[2 * i] = vb.x; hrb[2 * i + 1] = vb.y;
        }
    }
    ull ctxa[8], ctxb[8];
#pragma unroll
    for (int d = 0; d < 8; d++) { ctxa[d] = 0ull; ctxb[d] = 0ull; }

    for (int tile = 0; tile < 4; tile++) {
#pragma unroll 4
        for (int cc = 0; cc < 32; cc++) {
            const ulonglong2* zp = (const ulonglong2*)(zs + (tile * 32 + cc) * 16);
            ulonglong2 z0 = zp[0], z1 = zp[1], z2 = zp[2], z3 = zp[3];
            ull da0 = 0ull, da1 = 0ull, db0 = 0ull, db1 = 0ull;
            da0 = fma2_(hra[0], z0.x, da0); da1 = fma2_(hra[1], z0.y, da1);
            da0 = fma2_(hra[2], z1.x, da0); da1 = fma2_(hra[3], z1.y, da1);
            da0 = fma2_(hra[4], z2.x, da0); da1 = fma2_(hra[5], z2.y, da1);
            da0 = fma2_(hra[6], z3.x, da0); da1 = fma2_(hra[7], z3.y, da1);
            db0 = fma2_(hrb[0], z0.x, db0); db1 = fma2_(hrb[1], z0.y, db1);
            db0 = fma2_(hrb[2], z1.x, db0); db1 = fma2_(hrb[3], z1.y, db1);
            db0 = fma2_(hrb[4], z2.x, db0); db1 = fma2_(hrb[5], z2.y, db1);
            db0 = fma2_(hrb[6], z3.x, db0); db1 = fma2_(hrb[7], z3.y, db1);
            float2 a0 = unpk(da0), a1 = unpk(da1);
            float2 b0 = unpk(db0), b1 = unpk(db1);
            E[cc * K5A_EPAD + bq0] = __expf((a0.x + a0.y) + (a1.x + a1.y));
            E[cc * K5A_EPAD + bq1] = __expf((b0.x + b0.y) + (b1.x + b1.y));
        }
        __syncthreads();
        {
            int cc = tid >> 3, seg = tid & 7;
            float s0 = 0.0f, s1 = 0.0f;
            const float* ep = E + cc * K5A_EPAD + seg;
#pragma unroll 8
            for (int j = 0; j < 32; j++) {
                s0 += ep[16 * j + 0];
                s1 += ep[16 * j + 8];
            }
            red[tid] = s0 + s1;
        }
        __syncthreads();
        if (tid < 32) {
            float s = 0.0f;
#pragma unroll
            for (int r = 0; r < 8; r++) s += red[tid * 8 + r];
            inv[tid] = 1.0f / s;
        }
        __syncthreads();
#pragma unroll 4
        for (int cc = 0; cc < 32; cc++) {
            float ic = inv[cc];
            float wv0 = E[cc * K5A_EPAD + bq0] * ic;
            float wv1 = E[cc * K5A_EPAD + bq1] * ic;
            ull w0 = pack2(wv0), w1 = pack2(wv1);
            const ulonglong2* hp2 =
                (const ulonglong2*)(hs + (q * 128 + tile * 32 + cc) * 16);
            ulonglong2 h0 = hp2[0], h1 = hp2[1], h2 = hp2[2], h3 = hp2[3];
            ctxa[0] = fma2_(w0, h0.x, ctxa[0]); ctxa[1] = fma2_(w0, h0.y, ctxa[1]);
            ctxa[2] = fma2_(w0, h1.x, ctxa[2]); ctxa[3] = fma2_(w0, h1.y, ctxa[3]);
            ctxa[4] = fma2_(w0, h2.x, ctxa[4]); ctxa[5] = fma2_(w0, h2.y, ctxa[5]);
            ctxa[6] = fma2_(w0, h3.x, ctxa[6]); ctxa[7] = fma2_(w0, h3.y, ctxa[7]);
            ctxb[0] = fma2_(w1, h0.x, ctxb[0]); ctxb[1] = fma2_(w1, h0.y, ctxb[1]);
            ctxb[2] = fma2_(w1, h1.x, ctxb[2]); ctxb[3] = fma2_(w1, h1.y, ctxb[3]);
            ctxb[4] = fma2_(w1, h2.x, ctxb[4]); ctxb[5] = fma2_(w1, h2.y, ctxb[5]);
            ctxb[6] = fma2_(w1, h3.x, ctxb[6]); ctxb[7] = fma2_(w1, h3.y, ctxb[7]);
        }
        __syncthreads();
    }

    float* pa = g_part + ((size_t)blockIdx.x * BB + bq0) * 16;
    float* pb = g_part + ((size_t)blockIdx.x * BB + bq1) * 16;
#pragma unroll
    for (int i = 0; i < 4; i++) {
        float2 a0 = unpk(ctxa[2 * i]), a1 = unpk(ctxa[2 * i + 1]);
        *(float4*)(pa + 4 * i) = make_float4(a0.x, a0.y, a1.x, a1.y);
        float2 b0 = unpk(ctxb[2 * i]), b1 = unpk(ctxb[2 * i + 1]);
        *(float4*)(pb + 4 * i) = make_float4(b0.x, b0.y, b1.x, b1.y);
    }
}

// ---------------------------------------------------------------------------
// K5b: combine partials (fixed order -> deterministic) + scoring epilogue.
// ---------------------------------------------------------------------------
__global__ __launch_bounds__(512) void k5b_score(
    const float* __restrict__ Wh, const float* __restrict__ We,
    const float* __restrict__ Wv, float* __restrict__ out)
{
    __shared__ float ws[528];   // Wh[256] | We[256] | Wv[16]
    const int tid = threadIdx.x;
    const int t   = blockIdx.x;

    if (tid < 256)      ws[tid] = Wh[tid];
    else if (tid < 512) ws[tid] = We[tid - 256];
    if (tid < 16)       ws[512 + tid] = Wv[tid];
    __syncthreads();

    float hr[16], cx[16];
    {
        const float4* hp = (const float4*)(g_h + ((size_t)t * BB + tid) * 16);
#pragma unroll
        for (int i = 0; i < 4; i++) *(float4*)&hr[4 * i] = hp[i];
    }
#pragma unroll
    for (int d = 0; d < 16; d++) cx[d] = 0.0f;
#pragma unroll
    for (int q = 0; q < 4; q++) {
        const float4* pp =
            (const float4*)(g_part + ((size_t)(t * 4 + q) * BB + tid) * 16);
#pragma unroll
        for (int i = 0; i < 4; i++) {
            float4 v = pp[i];
            cx[4 * i + 0] += v.x; cx[4 * i + 1] += v.y;
            cx[4 * i + 2] += v.z; cx[4 * i + 3] += v.w;
        }
    }

    float p = 0.0f;
#pragma unroll
    for (int d = 0; d < 16; d++) {
        float s = 0.0f;
#pragma unroll
        for (int e = 0; e < 16; e++) s = fmaf(hr[e], ws[d * 16 + e], s);
#pragma unroll
        for (int e = 0; e < 16; e++) s = fmaf(cx[e], ws[256 + d * 16 + e], s);
        p = fmaf(tanh_ap(s), ws[512 + d], p);
    }
    out[(size_t)t * BB + tid] = sig_ap(p);
}

// ---------------------------------------------------------------------------
extern "C" void kernel_launch(void* const* d_in, const int* in_sizes, int n_in,
                              void* d_out, int out_size)
{
    const float* X     = (const float*)d_in[0];
    const float* Wih_f = (const float*)d_in[1];
    const float* Whh_f = (const float*)d_in[2];
    const float* bih_f = (const float*)d_in[3];
    const float* bhh_f = (const float*)d_in[4];
    const float* Wih_b = (const float*)d_in[5];
    const float* Whh_b = (const float*)d_in[6];
    const float* bih_b = (const float*)d_in[7];
    const float* bhh_b = (const float*)d_in[8];
    const float* Wih_p = (const float*)d_in[9];
    const float* Whh_p = (const float*)d_in[10];
    const float* bih_p = (const float*)d_in[11];
    const float* bhh_p = (const float*)d_in[12];
    const float* W_h   = (const float*)d_in[13];
    const float* W_e   = (const float*)d_in[14];
    const float* W_v   = (const float*)d_in[15];
    float* out = (float*)d_out;

    cudaFuncSetAttribute(k1_proj_mma, cudaFuncAttributeMaxDynamicSharedMemorySize,
                         K1_SMEM_TOTAL);
    cudaFuncSetAttribute(k5a_attn, cudaFuncAttributeMaxDynamicSharedMemorySize,
                         K5A_SMEM_BYTES);

    k0_wcvt<<<24, 256>>>(Wih_f, Wih_b);
    k1_proj_mma<<<512, 256, K1_SMEM_TOTAL>>>(X, bih_f, bhh_f, bih_b, bhh_b);
    k2_bilstm<<<256, 128>>>(Whh_f, Whh_b);
    k4_ptr<<<128, 128>>>(Wih_p, Whh_p, bih_p, bhh_p);
    k5a_attn<<<512, 256, K5A_SMEM_BYTES>>>();
    k5b_score<<<128, 512>>>(W_h, W_e, W_v, out);
}